// round 2
// baseline (speedup 1.0000x reference)
#include <cuda_runtime.h>
#include <math.h>

#define NB   2
#define CIN  256
#define Hh   96
#define Ww   96
#define HW   9216
#define BC   128
#define C4   512
#define C5   640
#define COUT 256
#define KMASK 4608   // 512*9

// ---- scratch (static device arrays; no allocation) ----
__device__ float g_cv1[(size_t)NB*C5*HW];      // conv1x1 out: ch 0..127 = cur, 128..639 = ltrb (post-IN in place)
__device__ float g_f4t[(size_t)NB*4*HW*BC];    // feat4 transposed: [n][border][hw][c]
__device__ float g_ltrb[(size_t)NB*C4*HW];     // border-align output in the reshaped [n][512][HW] layout
__device__ float g_mask[(size_t)NB*C5*HW];     // sigmoid(conv3x3)

// ============================================================================
// K1: fused conv1x1 (cur 128ch || ltrb 512ch) = GEMM [640,256] x [256,HW] + bias
// ============================================================================
__global__ __launch_bounds__(256) void k_conv1(const float* __restrict__ feat,
    const float* __restrict__ w_cur, const float* __restrict__ b_cur,
    const float* __restrict__ w_ltrb, const float* __restrict__ b_ltrb)
{
    __shared__ float As[16][128];
    __shared__ float Bs[16][132];
    const int c0  = blockIdx.y * 128;
    const int p0  = blockIdx.x * 128;
    const int n   = p0 / HW;
    const int hw0 = p0 - n * HW;
    const float* X = feat + (size_t)n * CIN * HW + hw0;
    const int tid = threadIdx.x;
    const int tm = tid >> 4, tn = tid & 15;

    float acc[8][8];
#pragma unroll
    for (int i = 0; i < 8; ++i)
#pragma unroll
        for (int j = 0; j < 8; ++j) acc[i][j] = 0.f;

    for (int k0 = 0; k0 < CIN; k0 += 16) {
#pragma unroll
        for (int l = 0; l < 8; ++l) {
            int idx = tid + l * 256;
            int m = idx >> 4, k = idx & 15;
            int c = c0 + m;
            As[k][m] = (c < BC) ? w_cur[c * CIN + k0 + k]
                                : w_ltrb[(c - BC) * CIN + k0 + k];
        }
#pragma unroll
        for (int l = 0; l < 8; ++l) {
            int idx = tid + l * 256;
            int k = idx >> 7, p = idx & 127;
            Bs[k][p] = X[(size_t)(k0 + k) * HW + p];
        }
        __syncthreads();
#pragma unroll
        for (int k = 0; k < 16; ++k) {
            float a[8], b[8];
#pragma unroll
            for (int i = 0; i < 8; ++i) a[i] = As[k][tm * 8 + i];
#pragma unroll
            for (int j = 0; j < 8; ++j) b[j] = Bs[k][tn * 8 + j];
#pragma unroll
            for (int i = 0; i < 8; ++i)
#pragma unroll
                for (int j = 0; j < 8; ++j) acc[i][j] += a[i] * b[j];
        }
        __syncthreads();
    }
#pragma unroll
    for (int i = 0; i < 8; ++i) {
        int c = c0 + tm * 8 + i;
        float bias = (c < BC) ? b_cur[c] : b_ltrb[c - BC];
        float* out = g_cv1 + ((size_t)n * C5 + c) * HW + hw0 + tn * 8;
#pragma unroll
        for (int j = 0; j < 8; ++j) out[j] = acc[i][j] + bias;
    }
}

// ============================================================================
// K2: instance norm (biased var, eps=1e-5) + ReLU, in place. One block per (n,c).
// ============================================================================
__global__ __launch_bounds__(256) void k_inorm()
{
    const int nc = blockIdx.x;          // n*C5 + c
    float4* base = (float4*)(g_cv1 + (size_t)nc * HW);
    const int tid = threadIdx.x;
    float s = 0.f, q = 0.f;
#pragma unroll
    for (int i = tid; i < HW / 4; i += 256) {
        float4 v = base[i];
        s += v.x + v.y + v.z + v.w;
        q += v.x * v.x + v.y * v.y + v.z * v.z + v.w * v.w;
    }
    __shared__ float ss[256], qq[256];
    ss[tid] = s; qq[tid] = q;
    __syncthreads();
    for (int off = 128; off > 0; off >>= 1) {
        if (tid < off) { ss[tid] += ss[tid + off]; qq[tid] += qq[tid + off]; }
        __syncthreads();
    }
    const float mean = ss[0] * (1.f / HW);
    const float var  = qq[0] * (1.f / HW) - mean * mean;
    const float rstd = rsqrtf(var + 1e-5f);
#pragma unroll
    for (int i = tid; i < HW / 4; i += 256) {
        float4 v = base[i];
        v.x = fmaxf((v.x - mean) * rstd, 0.f);
        v.y = fmaxf((v.y - mean) * rstd, 0.f);
        v.z = fmaxf((v.z - mean) * rstd, 0.f);
        v.w = fmaxf((v.w - mean) * rstd, 0.f);
        base[i] = v;
    }
}

// ============================================================================
// K2b: transpose feat4 (channels 128..639 of g_cv1) into [n][b][hw][c]
// ============================================================================
__global__ void k_transpose()
{
    __shared__ float t[32][33];
    const int n   = blockIdx.z;
    const int c0  = blockIdx.y * 32;    // 0..511 relative to feat4
    const int hw0 = blockIdx.x * 32;
    const int tx = threadIdx.x, ty = threadIdx.y;   // 32 x 8
    const float* src = g_cv1 + ((size_t)n * C5 + BC + c0) * HW + hw0;
#pragma unroll
    for (int r = 0; r < 4; ++r)
        t[ty + r * 8][tx] = src[(size_t)(ty + r * 8) * HW + tx];
    __syncthreads();
    const int b   = c0 >> 7;
    const int cc0 = c0 & 127;
    float* dst = g_f4t + (((size_t)n * 4 + b) * HW + hw0) * BC + cc0;
#pragma unroll
    for (int r = 0; r < 4; ++r)
        dst[(size_t)(ty + r * 8) * BC + tx] = t[tx][ty + r * 8];
}

// ============================================================================
// K3: BorderAlign. Block = (n,hw), thread = channel. Max over 11 bilinear
// samples per border. Output written directly in the reshape layout:
// flat = (c*HW + hw)*4 + b  -> one float4 store per thread.
// ============================================================================
__global__ __launch_bounds__(128) void k_border(const float* __restrict__ boxes)
{
    const int blk = blockIdx.x;
    const int n  = blk / HW;
    const int hw = blk - n * HW;
    const int t  = threadIdx.x;     // channel 0..127
    const float4 bx = *(const float4*)(boxes + ((size_t)n * HW + hw) * 4);
    const float x1 = bx.x, y1 = bx.y, x2 = bx.z, y2 = bx.w;
    const float bw = (x2 - x1) * 0.1f, bh = (y2 - y1) * 0.1f;
    const float sxA[4] = { x1, x1, x1, x2 };
    const float syA[4] = { y1, y1, y2, y1 };
    const float dxA[4] = { bw, 0.f, bw, 0.f };
    const float dyA[4] = { 0.f, bh, 0.f, bh };
    float o[4];
    const float* ftn = g_f4t + (size_t)n * 4 * HW * BC;
#pragma unroll
    for (int b = 0; b < 4; ++b) {
        const float* fb = ftn + (size_t)b * HW * BC + t;
        float m = -3.4e38f;
        for (int i = 0; i <= 10; ++i) {
            float x = sxA[b] + dxA[b] * (float)i;
            float y = syA[b] + dyA[b] * (float)i;
            bool valid = (x >= -1.f) && (x <= 96.f) && (y >= -1.f) && (y <= 96.f);
            float xc = fminf(fmaxf(x, 0.f), 95.f);
            float yc = fminf(fmaxf(y, 0.f), 95.f);
            int x0 = (int)floorf(xc); if (x0 > 95) x0 = 95;
            int y0 = (int)floorf(yc); if (y0 > 95) y0 = 95;
            int x1i = x0 + 1 > 95 ? 95 : x0 + 1;
            int y1i = y0 + 1 > 95 ? 95 : y0 + 1;
            float lx = (x0 >= 95) ? 0.f : (xc - (float)x0);
            float ly = (y0 >= 95) ? 0.f : (yc - (float)y0);
            float hx = 1.f - lx, hy = 1.f - ly;
            float v00 = fb[(size_t)(y0  * 96 + x0 ) * BC];
            float v01 = fb[(size_t)(y0  * 96 + x1i) * BC];
            float v10 = fb[(size_t)(y1i * 96 + x0 ) * BC];
            float v11 = fb[(size_t)(y1i * 96 + x1i) * BC];
            float val = v00 * hy * hx + v01 * hy * lx + v10 * ly * hx + v11 * ly * lx;
            if (!valid) val = 0.f;
            m = fmaxf(m, val);
        }
        o[b] = m;
    }
    float4 r; r.x = o[0]; r.y = o[1]; r.z = o[2]; r.w = o[3];
    *(float4*)(g_ltrb + (size_t)n * C4 * HW + ((size_t)t * HW + hw) * 4) = r;
}

// ============================================================================
// K4: conv3x3 (feat4 -> 640ch) as implicit GEMM [640,4608]x[4608,HW], sigmoid.
// ============================================================================
__global__ __launch_bounds__(256) void k_mask(const float* __restrict__ w_mask,
                                              const float* __restrict__ b_mask)
{
    __shared__ float As[32][128];
    __shared__ float Bs[32][132];
    const int c0  = blockIdx.y * 128;
    const int p0  = blockIdx.x * 128;
    const int n   = p0 / HW;
    const int hw0 = p0 - n * HW;
    const float* F = g_cv1 + ((size_t)n * C5 + BC) * HW;   // feat4 base (post IN+ReLU)
    const int tid = threadIdx.x;
    const int tm = tid >> 4, tn = tid & 15;

    // per-thread pixel decode for the 16 B-load rows this thread fills:
    // idx = tid + l*256 -> p = idx & 127 is fixed per l; precompute h,w per l.
    int ph[16], pw[16];
#pragma unroll
    for (int l = 0; l < 16; ++l) {
        int idx = tid + l * 256;
        int p = idx & 127;
        int hw = hw0 + p;
        ph[l] = hw / 96;
        pw[l] = hw - ph[l] * 96;
    }

    float acc[8][8];
#pragma unroll
    for (int i = 0; i < 8; ++i)
#pragma unroll
        for (int j = 0; j < 8; ++j) acc[i][j] = 0.f;

    for (int k0 = 0; k0 < KMASK; k0 += 32) {
#pragma unroll
        for (int l = 0; l < 16; ++l) {
            int idx = tid + l * 256;
            int m = idx >> 5, k = idx & 31;
            As[k][m] = w_mask[(size_t)(c0 + m) * KMASK + k0 + k];
        }
#pragma unroll
        for (int l = 0; l < 16; ++l) {
            int idx = tid + l * 256;
            int k = idx >> 7, p = idx & 127;
            int kk = k0 + k;
            int ci = kk / 9;
            int tap = kk - ci * 9;
            int dy = tap / 3 - 1;
            int dx = tap - (tap / 3) * 3 - 1;
            int hh = ph[l] + dy, ww = pw[l] + dx;
            float v = 0.f;
            if ((unsigned)hh < 96u && (unsigned)ww < 96u)
                v = F[(size_t)ci * HW + hh * 96 + ww];
            Bs[k][p] = v;
        }
        __syncthreads();
#pragma unroll
        for (int k = 0; k < 32; ++k) {
            float a[8], b[8];
#pragma unroll
            for (int i = 0; i < 8; ++i) a[i] = As[k][tm * 8 + i];
#pragma unroll
            for (int j = 0; j < 8; ++j) b[j] = Bs[k][tn * 8 + j];
#pragma unroll
            for (int i = 0; i < 8; ++i)
#pragma unroll
                for (int j = 0; j < 8; ++j) acc[i][j] += a[i] * b[j];
        }
        __syncthreads();
    }
#pragma unroll
    for (int i = 0; i < 8; ++i) {
        int c = c0 + tm * 8 + i;
        float bias = b_mask[c];
        float* out = g_mask + ((size_t)n * C5 + c) * HW + hw0 + tn * 8;
#pragma unroll
        for (int j = 0; j < 8; ++j) {
            float v = acc[i][j] + bias;
            out[j] = 1.f / (1.f + __expf(-v));
        }
    }
}

// ============================================================================
// K5: final conv1x1 [256,640] on (align*mask), product fused into B-load, ReLU.
// ============================================================================
__global__ __launch_bounds__(256) void k_final(const float* __restrict__ w_border,
    const float* __restrict__ b_border, float* __restrict__ out)
{
    __shared__ float As[32][128];
    __shared__ float Bs[32][132];
    const int c0  = blockIdx.y * 128;
    const int p0  = blockIdx.x * 128;
    const int n   = p0 / HW;
    const int hw0 = p0 - n * HW;
    const int tid = threadIdx.x;
    const int tm = tid >> 4, tn = tid & 15;

    float acc[8][8];
#pragma unroll
    for (int i = 0; i < 8; ++i)
#pragma unroll
        for (int j = 0; j < 8; ++j) acc[i][j] = 0.f;

    const float* ltrb_n = g_ltrb + (size_t)n * C4 * HW;
    const float* fms_n  = g_cv1  + (size_t)n * C5 * HW;   // ch 0..127 = fm_short
    const float* mask_n = g_mask + (size_t)n * C5 * HW;

    for (int k0 = 0; k0 < C5; k0 += 32) {
#pragma unroll
        for (int l = 0; l < 16; ++l) {
            int idx = tid + l * 256;
            int m = idx >> 5, k = idx & 31;
            As[k][m] = w_border[(size_t)(c0 + m) * C5 + k0 + k];
        }
#pragma unroll
        for (int l = 0; l < 16; ++l) {
            int idx = tid + l * 256;
            int k = idx >> 7, p = idx & 127;
            int kk = k0 + k;
            int hw = hw0 + p;
            float a = (kk < C4) ? ltrb_n[(size_t)kk * HW + hw]
                                : fms_n[(size_t)(kk - C4) * HW + hw];
            float msk = mask_n[(size_t)kk * HW + hw];
            Bs[k][p] = a * msk;
        }
        __syncthreads();
#pragma unroll
        for (int k = 0; k < 32; ++k) {
            float a[8], b[8];
#pragma unroll
            for (int i = 0; i < 8; ++i) a[i] = As[k][tm * 8 + i];
#pragma unroll
            for (int j = 0; j < 8; ++j) b[j] = Bs[k][tn * 8 + j];
#pragma unroll
            for (int i = 0; i < 8; ++i)
#pragma unroll
                for (int j = 0; j < 8; ++j) acc[i][j] += a[i] * b[j];
        }
        __syncthreads();
    }
#pragma unroll
    for (int i = 0; i < 8; ++i) {
        int c = c0 + tm * 8 + i;
        float bias = b_border[c];
        float* o = out + ((size_t)n * COUT + c) * HW + hw0 + tn * 8;
#pragma unroll
        for (int j = 0; j < 8; ++j) {
            float v = acc[i][j] + bias;
            o[j] = v > 0.f ? v : 0.f;
        }
    }
}

// ============================================================================
extern "C" void kernel_launch(void* const* d_in, const int* in_sizes, int n_in,
                              void* d_out, int out_size)
{
    const float* feature  = (const float*)d_in[0];
    const float* boxes    = (const float*)d_in[1];
    // d_in[2] = wh (unused by forward)
    const float* w_cur    = (const float*)d_in[3];
    const float* b_cur    = (const float*)d_in[4];
    const float* w_ltrb   = (const float*)d_in[5];
    const float* b_ltrb   = (const float*)d_in[6];
    const float* w_mask   = (const float*)d_in[7];
    const float* b_mask   = (const float*)d_in[8];
    const float* w_border = (const float*)d_in[9];
    const float* b_border = (const float*)d_in[10];
    float* out = (float*)d_out;

    k_conv1<<<dim3(144, 5), 256>>>(feature, w_cur, b_cur, w_ltrb, b_ltrb);
    k_inorm<<<NB * C5, 256>>>();
    k_transpose<<<dim3(288, 16, NB), dim3(32, 8)>>>();
    k_border<<<NB * HW, 128>>>(boxes);
    k_mask<<<dim3(144, 5), 256>>>(w_mask, b_mask);
    k_final<<<dim3(144, 2), 256>>>(w_border, b_border, out);
}

// round 5
// speedup vs baseline: 2.2072x; 2.2072x over previous
#include <cuda_runtime.h>
#include <math.h>
#include <stdint.h>

#define NB   2
#define CIN  256
#define Hh   96
#define Ww   96
#define HW   9216
#define BC   128
#define C4   512
#define C5   640
#define COUT 256
#define KMASK 4608   // 512*9

// ---- scratch (static device arrays; no allocation) ----
__device__ float g_cv1[(size_t)NB*C5*HW];      // conv1x1 out: ch 0..127 = cur, 128..639 = ltrb (post-IN in place)
__device__ float g_f4t[(size_t)NB*4*HW*BC];    // feat4 transposed: [n][border][hw][c]
__device__ float g_ltrb[(size_t)NB*C4*HW];     // border-align output in the reshaped [n][512][HW] layout
__device__ float g_mask[(size_t)NB*C5*HW];     // sigmoid(conv3x3)

// tf32 cvt: destination must be a .b32 register (ptxas rejects .f32 dst)
__device__ __forceinline__ uint32_t to_tf32(float x) {
    uint32_t y;
    asm("cvt.rna.tf32.f32 %0, %1;" : "=r"(y) : "f"(x));
    return y;
}

__device__ __forceinline__ void mma_tf32(float* c, const uint32_t* a, const uint32_t* b) {
    asm volatile(
        "mma.sync.aligned.m16n8k8.row.col.f32.tf32.tf32.f32 "
        "{%0,%1,%2,%3}, {%4,%5,%6,%7}, {%8,%9}, {%0,%1,%2,%3};"
        : "+f"(c[0]), "+f"(c[1]), "+f"(c[2]), "+f"(c[3])
        : "r"(a[0]), "r"(a[1]), "r"(a[2]), "r"(a[3]), "r"(b[0]), "r"(b[1]));
}

// ============================================================================
// K1: fused conv1x1 (cur 128ch || ltrb 512ch) = GEMM [640,256] x [256,HW] + bias
// ============================================================================
__global__ __launch_bounds__(256) void k_conv1(const float* __restrict__ feat,
    const float* __restrict__ w_cur, const float* __restrict__ b_cur,
    const float* __restrict__ w_ltrb, const float* __restrict__ b_ltrb)
{
    __shared__ float As[16][128];
    __shared__ float Bs[16][132];
    const int c0  = blockIdx.y * 128;
    const int p0  = blockIdx.x * 128;
    const int n   = p0 / HW;
    const int hw0 = p0 - n * HW;
    const float* X = feat + (size_t)n * CIN * HW + hw0;
    const int tid = threadIdx.x;
    const int tm = tid >> 4, tn = tid & 15;

    float acc[8][8];
#pragma unroll
    for (int i = 0; i < 8; ++i)
#pragma unroll
        for (int j = 0; j < 8; ++j) acc[i][j] = 0.f;

    for (int k0 = 0; k0 < CIN; k0 += 16) {
#pragma unroll
        for (int l = 0; l < 8; ++l) {
            int idx = tid + l * 256;
            int m = idx >> 4, k = idx & 15;
            int c = c0 + m;
            As[k][m] = (c < BC) ? w_cur[c * CIN + k0 + k]
                                : w_ltrb[(c - BC) * CIN + k0 + k];
        }
#pragma unroll
        for (int l = 0; l < 8; ++l) {
            int idx = tid + l * 256;
            int k = idx >> 7, p = idx & 127;
            Bs[k][p] = X[(size_t)(k0 + k) * HW + p];
        }
        __syncthreads();
#pragma unroll
        for (int k = 0; k < 16; ++k) {
            float a[8], b[8];
#pragma unroll
            for (int i = 0; i < 8; ++i) a[i] = As[k][tm * 8 + i];
#pragma unroll
            for (int j = 0; j < 8; ++j) b[j] = Bs[k][tn * 8 + j];
#pragma unroll
            for (int i = 0; i < 8; ++i)
#pragma unroll
                for (int j = 0; j < 8; ++j) acc[i][j] += a[i] * b[j];
        }
        __syncthreads();
    }
#pragma unroll
    for (int i = 0; i < 8; ++i) {
        int c = c0 + tm * 8 + i;
        float bias = (c < BC) ? b_cur[c] : b_ltrb[c - BC];
        float* out = g_cv1 + ((size_t)n * C5 + c) * HW + hw0 + tn * 8;
#pragma unroll
        for (int j = 0; j < 8; ++j) out[j] = acc[i][j] + bias;
    }
}

// ============================================================================
// K2: instance norm (biased var, eps=1e-5) + ReLU, in place. One block per (n,c).
// ============================================================================
__global__ __launch_bounds__(256) void k_inorm()
{
    const int nc = blockIdx.x;          // n*C5 + c
    float4* base = (float4*)(g_cv1 + (size_t)nc * HW);
    const int tid = threadIdx.x;
    float s = 0.f, q = 0.f;
#pragma unroll
    for (int i = tid; i < HW / 4; i += 256) {
        float4 v = base[i];
        s += v.x + v.y + v.z + v.w;
        q += v.x * v.x + v.y * v.y + v.z * v.z + v.w * v.w;
    }
    __shared__ float ss[256], qq[256];
    ss[tid] = s; qq[tid] = q;
    __syncthreads();
    for (int off = 128; off > 0; off >>= 1) {
        if (tid < off) { ss[tid] += ss[tid + off]; qq[tid] += qq[tid + off]; }
        __syncthreads();
    }
    const float mean = ss[0] * (1.f / HW);
    const float var  = qq[0] * (1.f / HW) - mean * mean;
    const float rstd = rsqrtf(var + 1e-5f);
#pragma unroll
    for (int i = tid; i < HW / 4; i += 256) {
        float4 v = base[i];
        v.x = fmaxf((v.x - mean) * rstd, 0.f);
        v.y = fmaxf((v.y - mean) * rstd, 0.f);
        v.z = fmaxf((v.z - mean) * rstd, 0.f);
        v.w = fmaxf((v.w - mean) * rstd, 0.f);
        base[i] = v;
    }
}

// ============================================================================
// K2b: transpose feat4 (channels 128..639 of g_cv1) into [n][b][hw][c]
// ============================================================================
__global__ void k_transpose()
{
    __shared__ float t[32][33];
    const int n   = blockIdx.z;
    const int c0  = blockIdx.y * 32;    // 0..511 relative to feat4
    const int hw0 = blockIdx.x * 32;
    const int tx = threadIdx.x, ty = threadIdx.y;   // 32 x 8
    const float* src = g_cv1 + ((size_t)n * C5 + BC + c0) * HW + hw0;
#pragma unroll
    for (int r = 0; r < 4; ++r)
        t[ty + r * 8][tx] = src[(size_t)(ty + r * 8) * HW + tx];
    __syncthreads();
    const int b   = c0 >> 7;
    const int cc0 = c0 & 127;
    float* dst = g_f4t + (((size_t)n * 4 + b) * HW + hw0) * BC + cc0;
#pragma unroll
    for (int r = 0; r < 4; ++r)
        dst[(size_t)(ty + r * 8) * BC + tx] = t[tx][ty + r * 8];
}

// ============================================================================
// K3: BorderAlign. Threads 0..43 precompute sample params (offsets + weights,
// weights zeroed when invalid) into smem; then thread = channel, 44 samples,
// 4 gathers + 4 FMA + max each. Output written in the reshape layout.
// ============================================================================
struct SampP { int o00, o01, o10, o11; float w00, w01, w10, w11; };

__global__ __launch_bounds__(128) void k_border(const float* __restrict__ boxes)
{
    __shared__ SampP sp[44];
    const int blk = blockIdx.x;
    const int n  = blk / HW;
    const int hw = blk - n * HW;
    const int t  = threadIdx.x;     // channel 0..127

    if (t < 44) {
        const int b = t / 11, i = t - b * 11;
        const float4 bx = *(const float4*)(boxes + ((size_t)n * HW + hw) * 4);
        const float bw = (bx.z - bx.x) * 0.1f, bh = (bx.w - bx.y) * 0.1f;
        const float sx = (b == 3) ? bx.z : bx.x;
        const float sy = (b == 2) ? bx.w : bx.y;
        const float dx = (b == 0 || b == 2) ? bw : 0.f;
        const float dy = (b == 1 || b == 3) ? bh : 0.f;
        const float x = sx + dx * (float)i;
        const float y = sy + dy * (float)i;
        const bool valid = (x >= -1.f) && (x <= 96.f) && (y >= -1.f) && (y <= 96.f);
        const float xc = fminf(fmaxf(x, 0.f), 95.f);
        const float yc = fminf(fmaxf(y, 0.f), 95.f);
        int x0 = (int)floorf(xc); if (x0 > 95) x0 = 95;
        int y0 = (int)floorf(yc); if (y0 > 95) y0 = 95;
        const int x1i = x0 + 1 > 95 ? 95 : x0 + 1;
        const int y1i = y0 + 1 > 95 ? 95 : y0 + 1;
        const float lx = (x0 >= 95) ? 0.f : (xc - (float)x0);
        const float ly = (y0 >= 95) ? 0.f : (yc - (float)y0);
        const float hx = 1.f - lx, hy = 1.f - ly;
        const float s = valid ? 1.f : 0.f;
        SampP p;
        p.o00 = (y0  * 96 + x0 ) * BC;
        p.o01 = (y0  * 96 + x1i) * BC;
        p.o10 = (y1i * 96 + x0 ) * BC;
        p.o11 = (y1i * 96 + x1i) * BC;
        p.w00 = hy * hx * s;
        p.w01 = hy * lx * s;
        p.w10 = ly * hx * s;
        p.w11 = ly * lx * s;
        sp[t] = p;
    }
    __syncthreads();

    const float* ftn = g_f4t + (size_t)n * 4 * HW * BC + t;
    float o[4];
#pragma unroll
    for (int b = 0; b < 4; ++b) {
        const float* fb = ftn + b * (HW * BC);
        float m = -3.4e38f;
#pragma unroll
        for (int i = 0; i < 11; ++i) {
            const SampP p = sp[b * 11 + i];
            float val = p.w00 * fb[p.o00];
            val = fmaf(p.w01, fb[p.o01], val);
            val = fmaf(p.w10, fb[p.o10], val);
            val = fmaf(p.w11, fb[p.o11], val);
            m = fmaxf(m, val);
        }
        o[b] = m;
    }
    float4 r; r.x = o[0]; r.y = o[1]; r.z = o[2]; r.w = o[3];
    *(float4*)(g_ltrb + (size_t)n * C4 * HW + ((size_t)t * HW + hw) * 4) = r;
}

// ============================================================================
// K4: conv3x3 (feat4 -> 640ch) as implicit GEMM [640,4608]x[4608,HW] on tf32
// tensor cores (mma.m16n8k8), sigmoid epilogue.
// Block 128x128x32 tile, 8 warps, warp tile 64(M)x32(N).
// ============================================================================
__global__ __launch_bounds__(256) void k_mask(const float* __restrict__ w_mask,
                                              const float* __restrict__ b_mask)
{
    __shared__ uint32_t As[128][36];   // [m][k] tf32 bits, pad 4: conflict-free
    __shared__ uint32_t Bs[32][136];   // [k][p] tf32 bits, pad 8: conflict-free
    const int c0  = blockIdx.y * 128;
    const int p0  = blockIdx.x * 128;
    const int n   = p0 / HW;
    const int hw0 = p0 - n * HW;
    const float* F = g_cv1 + ((size_t)n * C5 + BC) * HW;   // feat4 base (post IN+ReLU)
    const int tid  = threadIdx.x;
    const int lane = tid & 31;
    const int wid  = tid >> 5;
    const int warp_m = wid & 1;       // 0..1 -> M offset 0/64
    const int warp_n = wid >> 1;      // 0..3 -> N offset 0/32/64/96
    const int lr = lane >> 2;         // 0..7
    const int lq = lane & 3;          // 0..3

    // per-thread pixel decode for the 16 B-load rows (p fixed per l)
    int ph[16], pw[16];
#pragma unroll
    for (int l = 0; l < 16; ++l) {
        int idx = tid + l * 256;
        int p = idx & 127;
        int hw = hw0 + p;
        ph[l] = hw / 96;
        pw[l] = hw - ph[l] * 96;
    }

    float acc[4][4][4];
#pragma unroll
    for (int mt = 0; mt < 4; ++mt)
#pragma unroll
        for (int nt = 0; nt < 4; ++nt)
#pragma unroll
            for (int r = 0; r < 4; ++r) acc[mt][nt][r] = 0.f;

    for (int k0 = 0; k0 < KMASK; k0 += 32) {
#pragma unroll
        for (int l = 0; l < 16; ++l) {
            int idx = tid + l * 256;
            int m = idx >> 5, k = idx & 31;
            As[m][k] = to_tf32(w_mask[(size_t)(c0 + m) * KMASK + k0 + k]);
        }
#pragma unroll
        for (int l = 0; l < 16; ++l) {
            int idx = tid + l * 256;
            int k = idx >> 7, p = idx & 127;
            int kk = k0 + k;
            int ci = kk / 9;
            int tap = kk - ci * 9;
            int dy = tap / 3 - 1;
            int dx = tap - (tap / 3) * 3 - 1;
            int hh = ph[l] + dy, ww = pw[l] + dx;
            float v = 0.f;
            if ((unsigned)hh < 96u && (unsigned)ww < 96u)
                v = F[(size_t)ci * HW + hh * 96 + ww];
            Bs[k][p] = to_tf32(v);
        }
        __syncthreads();

#pragma unroll
        for (int ks = 0; ks < 4; ++ks) {
            const int kb = ks * 8;
            uint32_t afr[4][4], bfr[4][2];
#pragma unroll
            for (int mt = 0; mt < 4; ++mt) {
                int row = warp_m * 64 + mt * 16 + lr;
                afr[mt][0] = As[row][kb + lq];
                afr[mt][1] = As[row + 8][kb + lq];
                afr[mt][2] = As[row][kb + lq + 4];
                afr[mt][3] = As[row + 8][kb + lq + 4];
            }
#pragma unroll
            for (int nt = 0; nt < 4; ++nt) {
                int col = warp_n * 32 + nt * 8 + lr;
                bfr[nt][0] = Bs[kb + lq][col];
                bfr[nt][1] = Bs[kb + lq + 4][col];
            }
#pragma unroll
            for (int mt = 0; mt < 4; ++mt)
#pragma unroll
                for (int nt = 0; nt < 4; ++nt)
                    mma_tf32(acc[mt][nt], afr[mt], bfr[nt]);
        }
        __syncthreads();
    }

    // Epilogue: c0r: row=lr, col=2*lq; c1: col+1; c2: row+8; c3: row+8,col+1
#pragma unroll
    for (int mt = 0; mt < 4; ++mt) {
        int c_lo = c0 + warp_m * 64 + mt * 16 + lr;
        int c_hi = c_lo + 8;
        float bias_lo = b_mask[c_lo];
        float bias_hi = b_mask[c_hi];
#pragma unroll
        for (int nt = 0; nt < 4; ++nt) {
            int p = hw0 + warp_n * 32 + nt * 8 + 2 * lq;
            float v0 = acc[mt][nt][0] + bias_lo;
            float v1 = acc[mt][nt][1] + bias_lo;
            float v2 = acc[mt][nt][2] + bias_hi;
            float v3 = acc[mt][nt][3] + bias_hi;
            float2 lo, hi;
            lo.x = 1.f / (1.f + __expf(-v0));
            lo.y = 1.f / (1.f + __expf(-v1));
            hi.x = 1.f / (1.f + __expf(-v2));
            hi.y = 1.f / (1.f + __expf(-v3));
            *(float2*)(g_mask + ((size_t)n * C5 + c_lo) * HW + p) = lo;
            *(float2*)(g_mask + ((size_t)n * C5 + c_hi) * HW + p) = hi;
        }
    }
}

// ============================================================================
// K5: final conv1x1 [256,640] on (align*mask), product fused into B-load, ReLU.
// ============================================================================
__global__ __launch_bounds__(256) void k_final(const float* __restrict__ w_border,
    const float* __restrict__ b_border, float* __restrict__ out)
{
    __shared__ float As[32][128];
    __shared__ float Bs[32][132];
    const int c0  = blockIdx.y * 128;
    const int p0  = blockIdx.x * 128;
    const int n   = p0 / HW;
    const int hw0 = p0 - n * HW;
    const int tid = threadIdx.x;
    const int tm = tid >> 4, tn = tid & 15;

    float acc[8][8];
#pragma unroll
    for (int i = 0; i < 8; ++i)
#pragma unroll
        for (int j = 0; j < 8; ++j) acc[i][j] = 0.f;

    const float* ltrb_n = g_ltrb + (size_t)n * C4 * HW;
    const float* fms_n  = g_cv1  + (size_t)n * C5 * HW;   // ch 0..127 = fm_short
    const float* mask_n = g_mask + (size_t)n * C5 * HW;

    for (int k0 = 0; k0 < C5; k0 += 32) {
#pragma unroll
        for (int l = 0; l < 16; ++l) {
            int idx = tid + l * 256;
            int m = idx >> 5, k = idx & 31;
            As[k][m] = w_border[(size_t)(c0 + m) * C5 + k0 + k];
        }
#pragma unroll
        for (int l = 0; l < 16; ++l) {
            int idx = tid + l * 256;
            int k = idx >> 7, p = idx & 127;
            int kk = k0 + k;
            int hw = hw0 + p;
            float a = (kk < C4) ? ltrb_n[(size_t)kk * HW + hw]
                                : fms_n[(size_t)(kk - C4) * HW + hw];
            float msk = mask_n[(size_t)kk * HW + hw];
            Bs[k][p] = a * msk;
        }
        __syncthreads();
#pragma unroll
        for (int k = 0; k < 32; ++k) {
            float a[8], b[8];
#pragma unroll
            for (int i = 0; i < 8; ++i) a[i] = As[k][tm * 8 + i];
#pragma unroll
            for (int j = 0; j < 8; ++j) b[j] = Bs[k][tn * 8 + j];
#pragma unroll
            for (int i = 0; i < 8; ++i)
#pragma unroll
                for (int j = 0; j < 8; ++j) acc[i][j] += a[i] * b[j];
        }
        __syncthreads();
    }
#pragma unroll
    for (int i = 0; i < 8; ++i) {
        int c = c0 + tm * 8 + i;
        float bias = b_border[c];
        float* o = out + ((size_t)n * COUT + c) * HW + hw0 + tn * 8;
#pragma unroll
        for (int j = 0; j < 8; ++j) {
            float v = acc[i][j] + bias;
            o[j] = v > 0.f ? v : 0.f;
        }
    }
}

// ============================================================================
extern "C" void kernel_launch(void* const* d_in, const int* in_sizes, int n_in,
                              void* d_out, int out_size)
{
    const float* feature  = (const float*)d_in[0];
    const float* boxes    = (const float*)d_in[1];
    // d_in[2] = wh (unused by forward)
    const float* w_cur    = (const float*)d_in[3];
    const float* b_cur    = (const float*)d_in[4];
    const float* w_ltrb   = (const float*)d_in[5];
    const float* b_ltrb   = (const float*)d_in[6];
    const float* w_mask   = (const float*)d_in[7];
    const float* b_mask   = (const float*)d_in[8];
    const float* w_border = (const float*)d_in[9];
    const float* b_border = (const float*)d_in[10];
    float* out = (float*)d_out;

    k_conv1<<<dim3(144, 5), 256>>>(feature, w_cur, b_cur, w_ltrb, b_ltrb);
    k_inorm<<<NB * C5, 256>>>();
    k_transpose<<<dim3(288, 16, NB), dim3(32, 8)>>>();
    k_border<<<NB * HW, 128>>>(boxes);
    k_mask<<<dim3(144, 5), 256>>>(w_mask, b_mask);
    k_final<<<dim3(144, 2), 256>>>(w_border, b_border, out);
}

// round 6
// speedup vs baseline: 2.7403x; 1.2415x over previous
#include <cuda_runtime.h>
#include <math.h>
#include <stdint.h>

#define NB   2
#define CIN  256
#define Hh   96
#define Ww   96
#define HW   9216
#define BC   128
#define C4   512
#define C5   640
#define COUT 256
#define KMASK 4608   // 512*9

// ---- scratch (static device arrays; no allocation) ----
__device__ float g_cv1[(size_t)NB*C5*HW];      // conv1x1 out: ch 0..127 = cur, 128..639 = ltrb (post-IN in place)
__device__ float g_f4t[(size_t)NB*4*HW*BC];    // feat4 transposed: [n][border][hw][c]
__device__ float g_ltrb[(size_t)NB*C4*HW];     // border-align output in the reshaped [n][512][HW] layout
__device__ float g_mask[(size_t)NB*C5*HW];     // sigmoid(conv3x3)

// tf32 cvt: destination must be a .b32 register
__device__ __forceinline__ uint32_t to_tf32(float x) {
    uint32_t y;
    asm("cvt.rna.tf32.f32 %0, %1;" : "=r"(y) : "f"(x));
    return y;
}

__device__ __forceinline__ void mma_tf32(float* c, const uint32_t* a, const uint32_t* b) {
    asm volatile(
        "mma.sync.aligned.m16n8k8.row.col.f32.tf32.tf32.f32 "
        "{%0,%1,%2,%3}, {%4,%5,%6,%7}, {%8,%9}, {%0,%1,%2,%3};"
        : "+f"(c[0]), "+f"(c[1]), "+f"(c[2]), "+f"(c[3])
        : "r"(a[0]), "r"(a[1]), "r"(a[2]), "r"(a[3]), "r"(b[0]), "r"(b[1]));
}

// ============================================================================
// K1: fused conv1x1 (cur||ltrb) = GEMM [640,256]x[256,HW] + bias, tf32 mma,
// register-prefetch pipelined. Block tile 128x128x32, 8 warps (64x32 warp tile).
// ============================================================================
__global__ __launch_bounds__(256) void k_conv1(const float* __restrict__ feat,
    const float* __restrict__ w_cur, const float* __restrict__ b_cur,
    const float* __restrict__ w_ltrb, const float* __restrict__ b_ltrb)
{
    __shared__ uint32_t As[128][36];
    __shared__ uint32_t Bs[32][136];
    const int c0  = blockIdx.y * 128;
    const int p0  = blockIdx.x * 128;
    const int n   = p0 / HW;
    const int hw0 = p0 - n * HW;
    const float* X = feat + (size_t)n * CIN * HW + hw0;
    const int tid  = threadIdx.x;
    const int lane = tid & 31;
    const int wid  = tid >> 5;
    const int warp_m = wid & 1;
    const int warp_n = wid >> 1;
    const int lr = lane >> 2;
    const int lq = lane & 3;

    float acc[4][4][4];
#pragma unroll
    for (int mt = 0; mt < 4; ++mt)
#pragma unroll
        for (int nt = 0; nt < 4; ++nt)
#pragma unroll
            for (int r = 0; r < 4; ++r) acc[mt][nt][r] = 0.f;

    float rA[16], rB[16];
    // prologue: tile 0
#pragma unroll
    for (int l = 0; l < 16; ++l) {
        int idx = tid + l * 256;
        int m = idx >> 5, k = idx & 31;
        int c = c0 + m;
        rA[l] = (c < BC) ? w_cur[c * CIN + k] : w_ltrb[(c - BC) * CIN + k];
    }
#pragma unroll
    for (int l = 0; l < 16; ++l) {
        int idx = tid + l * 256;
        int k = idx >> 7, p = idx & 127;
        rB[l] = X[(size_t)k * HW + p];
    }

    for (int kt = 0; kt < CIN / 32; ++kt) {
#pragma unroll
        for (int l = 0; l < 16; ++l) {
            int idx = tid + l * 256;
            As[idx >> 5][idx & 31] = to_tf32(rA[l]);
        }
#pragma unroll
        for (int l = 0; l < 16; ++l) {
            int idx = tid + l * 256;
            Bs[idx >> 7][idx & 127] = to_tf32(rB[l]);
        }
        __syncthreads();
        if (kt + 1 < CIN / 32) {
            int k0 = (kt + 1) * 32;
#pragma unroll
            for (int l = 0; l < 16; ++l) {
                int idx = tid + l * 256;
                int m = idx >> 5, k = idx & 31;
                int c = c0 + m;
                rA[l] = (c < BC) ? w_cur[c * CIN + k0 + k]
                                 : w_ltrb[(c - BC) * CIN + k0 + k];
            }
#pragma unroll
            for (int l = 0; l < 16; ++l) {
                int idx = tid + l * 256;
                int k = idx >> 7, p = idx & 127;
                rB[l] = X[(size_t)(k0 + k) * HW + p];
            }
        }
#pragma unroll
        for (int ks = 0; ks < 4; ++ks) {
            const int kb = ks * 8;
            uint32_t afr[4][4], bfr[4][2];
#pragma unroll
            for (int mt = 0; mt < 4; ++mt) {
                int row = warp_m * 64 + mt * 16 + lr;
                afr[mt][0] = As[row][kb + lq];
                afr[mt][1] = As[row + 8][kb + lq];
                afr[mt][2] = As[row][kb + lq + 4];
                afr[mt][3] = As[row + 8][kb + lq + 4];
            }
#pragma unroll
            for (int nt = 0; nt < 4; ++nt) {
                int col = warp_n * 32 + nt * 8 + lr;
                bfr[nt][0] = Bs[kb + lq][col];
                bfr[nt][1] = Bs[kb + lq + 4][col];
            }
#pragma unroll
            for (int mt = 0; mt < 4; ++mt)
#pragma unroll
                for (int nt = 0; nt < 4; ++nt)
                    mma_tf32(acc[mt][nt], afr[mt], bfr[nt]);
        }
        __syncthreads();
    }

#pragma unroll
    for (int mt = 0; mt < 4; ++mt) {
        int c_lo = c0 + warp_m * 64 + mt * 16 + lr;
        int c_hi = c_lo + 8;
        float bias_lo = (c_lo < BC) ? b_cur[c_lo] : b_ltrb[c_lo - BC];
        float bias_hi = (c_hi < BC) ? b_cur[c_hi] : b_ltrb[c_hi - BC];
#pragma unroll
        for (int nt = 0; nt < 4; ++nt) {
            int p = hw0 + warp_n * 32 + nt * 8 + 2 * lq;
            float2 lo, hi;
            lo.x = acc[mt][nt][0] + bias_lo;
            lo.y = acc[mt][nt][1] + bias_lo;
            hi.x = acc[mt][nt][2] + bias_hi;
            hi.y = acc[mt][nt][3] + bias_hi;
            *(float2*)(g_cv1 + ((size_t)n * C5 + c_lo) * HW + p) = lo;
            *(float2*)(g_cv1 + ((size_t)n * C5 + c_hi) * HW + p) = hi;
        }
    }
}

// ============================================================================
// K2: instance norm (biased var, eps=1e-5) + ReLU, in place. One block per (n,c).
// ============================================================================
__global__ __launch_bounds__(256) void k_inorm()
{
    const int nc = blockIdx.x;          // n*C5 + c
    float4* base = (float4*)(g_cv1 + (size_t)nc * HW);
    const int tid = threadIdx.x;
    float s = 0.f, q = 0.f;
#pragma unroll
    for (int i = tid; i < HW / 4; i += 256) {
        float4 v = base[i];
        s += v.x + v.y + v.z + v.w;
        q += v.x * v.x + v.y * v.y + v.z * v.z + v.w * v.w;
    }
    __shared__ float ss[256], qq[256];
    ss[tid] = s; qq[tid] = q;
    __syncthreads();
    for (int off = 128; off > 0; off >>= 1) {
        if (tid < off) { ss[tid] += ss[tid + off]; qq[tid] += qq[tid + off]; }
        __syncthreads();
    }
    const float mean = ss[0] * (1.f / HW);
    const float var  = qq[0] * (1.f / HW) - mean * mean;
    const float rstd = rsqrtf(var + 1e-5f);
#pragma unroll
    for (int i = tid; i < HW / 4; i += 256) {
        float4 v = base[i];
        v.x = fmaxf((v.x - mean) * rstd, 0.f);
        v.y = fmaxf((v.y - mean) * rstd, 0.f);
        v.z = fmaxf((v.z - mean) * rstd, 0.f);
        v.w = fmaxf((v.w - mean) * rstd, 0.f);
        base[i] = v;
    }
}

// ============================================================================
// K2b: transpose feat4 (channels 128..639 of g_cv1) into [n][b][hw][c]
// ============================================================================
__global__ void k_transpose()
{
    __shared__ float t[32][33];
    const int n   = blockIdx.z;
    const int c0  = blockIdx.y * 32;    // 0..511 relative to feat4
    const int hw0 = blockIdx.x * 32;
    const int tx = threadIdx.x, ty = threadIdx.y;   // 32 x 8
    const float* src = g_cv1 + ((size_t)n * C5 + BC + c0) * HW + hw0;
#pragma unroll
    for (int r = 0; r < 4; ++r)
        t[ty + r * 8][tx] = src[(size_t)(ty + r * 8) * HW + tx];
    __syncthreads();
    const int b   = c0 >> 7;
    const int cc0 = c0 & 127;
    float* dst = g_f4t + (((size_t)n * 4 + b) * HW + hw0) * BC + cc0;
#pragma unroll
    for (int r = 0; r < 4; ++r)
        dst[(size_t)(ty + r * 8) * BC + tx] = t[tx][ty + r * 8];
}

// ============================================================================
// K3: BorderAlign. 2 pixels per block; threads 0..87 precompute sample params;
// each thread then handles 2 channels (float2 gathers) for one pixel.
// ============================================================================
struct SampP { int o00, o01, o10, o11; float w00, w01, w10, w11; };

__global__ __launch_bounds__(128) void k_border(const float* __restrict__ boxes)
{
    __shared__ SampP sp[2][44];
    const int blk = blockIdx.x;         // pixel pair
    const int t  = threadIdx.x;

    if (t < 88) {
        const int pix = t / 44, s = t - pix * 44;
        const int b = s / 11, i = s - b * 11;
        const int P = blk * 2 + pix;
        const int n = P / HW, hw = P - n * HW;
        const float4 bx = *(const float4*)(boxes + ((size_t)n * HW + hw) * 4);
        const float bw = (bx.z - bx.x) * 0.1f, bh = (bx.w - bx.y) * 0.1f;
        const float sx = (b == 3) ? bx.z : bx.x;
        const float sy = (b == 2) ? bx.w : bx.y;
        const float dx = (b == 0 || b == 2) ? bw : 0.f;
        const float dy = (b == 1 || b == 3) ? bh : 0.f;
        const float x = sx + dx * (float)i;
        const float y = sy + dy * (float)i;
        const bool valid = (x >= -1.f) && (x <= 96.f) && (y >= -1.f) && (y <= 96.f);
        const float xc = fminf(fmaxf(x, 0.f), 95.f);
        const float yc = fminf(fmaxf(y, 0.f), 95.f);
        int x0 = (int)floorf(xc); if (x0 > 95) x0 = 95;
        int y0 = (int)floorf(yc); if (y0 > 95) y0 = 95;
        const int x1i = x0 + 1 > 95 ? 95 : x0 + 1;
        const int y1i = y0 + 1 > 95 ? 95 : y0 + 1;
        const float lx = (x0 >= 95) ? 0.f : (xc - (float)x0);
        const float ly = (y0 >= 95) ? 0.f : (yc - (float)y0);
        const float hx = 1.f - lx, hy = 1.f - ly;
        const float sv = valid ? 1.f : 0.f;
        SampP p;
        p.o00 = (y0  * 96 + x0 ) * BC;
        p.o01 = (y0  * 96 + x1i) * BC;
        p.o10 = (y1i * 96 + x0 ) * BC;
        p.o11 = (y1i * 96 + x1i) * BC;
        p.w00 = hy * hx * sv;
        p.w01 = hy * lx * sv;
        p.w10 = ly * hx * sv;
        p.w11 = ly * lx * sv;
        sp[pix][s] = p;
    }
    __syncthreads();

    const int half = t >> 6;            // which pixel of the pair
    const int ch   = (t & 63) * 2;      // channel pair
    const int P = blk * 2 + half;
    const int n = P / HW, hw = P - n * HW;
    const float* ftn = g_f4t + (size_t)n * 4 * HW * BC + ch;
    float2 o[4];
#pragma unroll
    for (int b = 0; b < 4; ++b) {
        const float* fb = ftn + b * (HW * BC);
        float mx = -3.4e38f, my = -3.4e38f;
#pragma unroll
        for (int i = 0; i < 11; ++i) {
            const SampP p = sp[half][b * 11 + i];
            const float2 v00 = *(const float2*)(fb + p.o00);
            const float2 v01 = *(const float2*)(fb + p.o01);
            const float2 v10 = *(const float2*)(fb + p.o10);
            const float2 v11 = *(const float2*)(fb + p.o11);
            float vx = p.w00 * v00.x;
            vx = fmaf(p.w01, v01.x, vx);
            vx = fmaf(p.w10, v10.x, vx);
            vx = fmaf(p.w11, v11.x, vx);
            float vy = p.w00 * v00.y;
            vy = fmaf(p.w01, v01.y, vy);
            vy = fmaf(p.w10, v10.y, vy);
            vy = fmaf(p.w11, v11.y, vy);
            mx = fmaxf(mx, vx);
            my = fmaxf(my, vy);
        }
        o[b].x = mx; o[b].y = my;
    }
    float* base = g_ltrb + (size_t)n * C4 * HW;
    float4 r0; r0.x = o[0].x; r0.y = o[1].x; r0.z = o[2].x; r0.w = o[3].x;
    float4 r1; r1.x = o[0].y; r1.y = o[1].y; r1.z = o[2].y; r1.w = o[3].y;
    *(float4*)(base + ((size_t)ch       * HW + hw) * 4) = r0;
    *(float4*)(base + ((size_t)(ch + 1) * HW + hw) * 4) = r1;
}

// ============================================================================
// K4: conv3x3 (feat4 -> 640ch) as implicit GEMM [640,4608]x[4608,HW] on tf32
// tensor cores, register-prefetch pipelined, sigmoid epilogue.
// ============================================================================
__global__ __launch_bounds__(256) void k_mask(const float* __restrict__ w_mask,
                                              const float* __restrict__ b_mask)
{
    __shared__ uint32_t As[128][36];
    __shared__ uint32_t Bs[32][136];
    const int c0  = blockIdx.y * 128;
    const int p0  = blockIdx.x * 128;
    const int n   = p0 / HW;
    const int hw0 = p0 - n * HW;
    const float* F = g_cv1 + ((size_t)n * C5 + BC) * HW;   // feat4 (post IN+ReLU)
    const int tid  = threadIdx.x;
    const int lane = tid & 31;
    const int wid  = tid >> 5;
    const int warp_m = wid & 1;
    const int warp_n = wid >> 1;
    const int lr = lane >> 2;
    const int lq = lane & 3;

    int ph[16], pw[16];
#pragma unroll
    for (int l = 0; l < 16; ++l) {
        int idx = tid + l * 256;
        int p = idx & 127;
        int hw = hw0 + p;
        ph[l] = hw / 96;
        pw[l] = hw - ph[l] * 96;
    }

    float acc[4][4][4];
#pragma unroll
    for (int mt = 0; mt < 4; ++mt)
#pragma unroll
        for (int nt = 0; nt < 4; ++nt)
#pragma unroll
            for (int r = 0; r < 4; ++r) acc[mt][nt][r] = 0.f;

    float rA[16], rB[16];
    // prologue: tile 0
#pragma unroll
    for (int l = 0; l < 16; ++l) {
        int idx = tid + l * 256;
        int m = idx >> 5, k = idx & 31;
        rA[l] = w_mask[(size_t)(c0 + m) * KMASK + k];
    }
#pragma unroll
    for (int l = 0; l < 16; ++l) {
        int idx = tid + l * 256;
        int k = idx >> 7;
        int ci = k / 9;
        int tap = k - ci * 9;
        int dy = tap / 3 - 1;
        int dx = tap - (tap / 3) * 3 - 1;
        int hh = ph[l] + dy, ww = pw[l] + dx;
        float v = 0.f;
        if ((unsigned)hh < 96u && (unsigned)ww < 96u)
            v = F[(size_t)ci * HW + hh * 96 + ww];
        rB[l] = v;
    }

    const int NT = KMASK / 32;
    for (int kt = 0; kt < NT; ++kt) {
#pragma unroll
        for (int l = 0; l < 16; ++l) {
            int idx = tid + l * 256;
            As[idx >> 5][idx & 31] = to_tf32(rA[l]);
        }
#pragma unroll
        for (int l = 0; l < 16; ++l) {
            int idx = tid + l * 256;
            Bs[idx >> 7][idx & 127] = to_tf32(rB[l]);
        }
        __syncthreads();
        if (kt + 1 < NT) {
            int k0 = (kt + 1) * 32;
#pragma unroll
            for (int l = 0; l < 16; ++l) {
                int idx = tid + l * 256;
                int m = idx >> 5, k = idx & 31;
                rA[l] = w_mask[(size_t)(c0 + m) * KMASK + k0 + k];
            }
#pragma unroll
            for (int l = 0; l < 16; ++l) {
                int idx = tid + l * 256;
                int kk = k0 + (idx >> 7);
                int ci = kk / 9;
                int tap = kk - ci * 9;
                int dy = tap / 3 - 1;
                int dx = tap - (tap / 3) * 3 - 1;
                int hh = ph[l] + dy, ww = pw[l] + dx;
                float v = 0.f;
                if ((unsigned)hh < 96u && (unsigned)ww < 96u)
                    v = F[(size_t)ci * HW + hh * 96 + ww];
                rB[l] = v;
            }
        }
#pragma unroll
        for (int ks = 0; ks < 4; ++ks) {
            const int kb = ks * 8;
            uint32_t afr[4][4], bfr[4][2];
#pragma unroll
            for (int mt = 0; mt < 4; ++mt) {
                int row = warp_m * 64 + mt * 16 + lr;
                afr[mt][0] = As[row][kb + lq];
                afr[mt][1] = As[row + 8][kb + lq];
                afr[mt][2] = As[row][kb + lq + 4];
                afr[mt][3] = As[row + 8][kb + lq + 4];
            }
#pragma unroll
            for (int nt = 0; nt < 4; ++nt) {
                int col = warp_n * 32 + nt * 8 + lr;
                bfr[nt][0] = Bs[kb + lq][col];
                bfr[nt][1] = Bs[kb + lq + 4][col];
            }
#pragma unroll
            for (int mt = 0; mt < 4; ++mt)
#pragma unroll
                for (int nt = 0; nt < 4; ++nt)
                    mma_tf32(acc[mt][nt], afr[mt], bfr[nt]);
        }
        __syncthreads();
    }

#pragma unroll
    for (int mt = 0; mt < 4; ++mt) {
        int c_lo = c0 + warp_m * 64 + mt * 16 + lr;
        int c_hi = c_lo + 8;
        float bias_lo = b_mask[c_lo];
        float bias_hi = b_mask[c_hi];
#pragma unroll
        for (int nt = 0; nt < 4; ++nt) {
            int p = hw0 + warp_n * 32 + nt * 8 + 2 * lq;
            float v0 = acc[mt][nt][0] + bias_lo;
            float v1 = acc[mt][nt][1] + bias_lo;
            float v2 = acc[mt][nt][2] + bias_hi;
            float v3 = acc[mt][nt][3] + bias_hi;
            float2 lo, hi;
            lo.x = 1.f / (1.f + __expf(-v0));
            lo.y = 1.f / (1.f + __expf(-v1));
            hi.x = 1.f / (1.f + __expf(-v2));
            hi.y = 1.f / (1.f + __expf(-v3));
            *(float2*)(g_mask + ((size_t)n * C5 + c_lo) * HW + p) = lo;
            *(float2*)(g_mask + ((size_t)n * C5 + c_hi) * HW + p) = hi;
        }
    }
}

// ============================================================================
// K5: final conv1x1 [256,640] on (align*mask), tf32 mma, pipelined, ReLU.
// ============================================================================
__global__ __launch_bounds__(256) void k_final(const float* __restrict__ w_border,
    const float* __restrict__ b_border, float* __restrict__ out)
{
    __shared__ uint32_t As[128][36];
    __shared__ uint32_t Bs[32][136];
    const int c0  = blockIdx.y * 128;
    const int p0  = blockIdx.x * 128;
    const int n   = p0 / HW;
    const int hw0 = p0 - n * HW;
    const int tid  = threadIdx.x;
    const int lane = tid & 31;
    const int wid  = tid >> 5;
    const int warp_m = wid & 1;
    const int warp_n = wid >> 1;
    const int lr = lane >> 2;
    const int lq = lane & 3;

    const float* ltrb_n = g_ltrb + (size_t)n * C4 * HW;
    const float* fms_n  = g_cv1  + (size_t)n * C5 * HW;   // ch 0..127 = fm_short
    const float* mask_n = g_mask + (size_t)n * C5 * HW;

    float acc[4][4][4];
#pragma unroll
    for (int mt = 0; mt < 4; ++mt)
#pragma unroll
        for (int nt = 0; nt < 4; ++nt)
#pragma unroll
            for (int r = 0; r < 4; ++r) acc[mt][nt][r] = 0.f;

    float rA[16], rBa[16], rBm[16];
#pragma unroll
    for (int l = 0; l < 16; ++l) {
        int idx = tid + l * 256;
        int m = idx >> 5, k = idx & 31;
        rA[l] = w_border[(size_t)(c0 + m) * C5 + k];
    }
#pragma unroll
    for (int l = 0; l < 16; ++l) {
        int idx = tid + l * 256;
        int k = idx >> 7, p = idx & 127;
        int hw = hw0 + p;
        rBa[l] = (k < C4) ? ltrb_n[(size_t)k * HW + hw]
                          : fms_n[(size_t)(k - C4) * HW + hw];
        rBm[l] = mask_n[(size_t)k * HW + hw];
    }

    const int NT = C5 / 32;
    for (int kt = 0; kt < NT; ++kt) {
#pragma unroll
        for (int l = 0; l < 16; ++l) {
            int idx = tid + l * 256;
            As[idx >> 5][idx & 31] = to_tf32(rA[l]);
        }
#pragma unroll
        for (int l = 0; l < 16; ++l) {
            int idx = tid + l * 256;
            Bs[idx >> 7][idx & 127] = to_tf32(rBa[l] * rBm[l]);
        }
        __syncthreads();
        if (kt + 1 < NT) {
            int k0 = (kt + 1) * 32;
#pragma unroll
            for (int l = 0; l < 16; ++l) {
                int idx = tid + l * 256;
                int m = idx >> 5, k = idx & 31;
                rA[l] = w_border[(size_t)(c0 + m) * C5 + k0 + k];
            }
#pragma unroll
            for (int l = 0; l < 16; ++l) {
                int idx = tid + l * 256;
                int kk = k0 + (idx >> 7);
                int hw = hw0 + (idx & 127);
                rBa[l] = (kk < C4) ? ltrb_n[(size_t)kk * HW + hw]
                                   : fms_n[(size_t)(kk - C4) * HW + hw];
                rBm[l] = mask_n[(size_t)kk * HW + hw];
            }
        }
#pragma unroll
        for (int ks = 0; ks < 4; ++ks) {
            const int kb = ks * 8;
            uint32_t afr[4][4], bfr[4][2];
#pragma unroll
            for (int mt = 0; mt < 4; ++mt) {
                int row = warp_m * 64 + mt * 16 + lr;
                afr[mt][0] = As[row][kb + lq];
                afr[mt][1] = As[row + 8][kb + lq];
                afr[mt][2] = As[row][kb + lq + 4];
                afr[mt][3] = As[row + 8][kb + lq + 4];
            }
#pragma unroll
            for (int nt = 0; nt < 4; ++nt) {
                int col = warp_n * 32 + nt * 8 + lr;
                bfr[nt][0] = Bs[kb + lq][col];
                bfr[nt][1] = Bs[kb + lq + 4][col];
            }
#pragma unroll
            for (int mt = 0; mt < 4; ++mt)
#pragma unroll
                for (int nt = 0; nt < 4; ++nt)
                    mma_tf32(acc[mt][nt], afr[mt], bfr[nt]);
        }
        __syncthreads();
    }

#pragma unroll
    for (int mt = 0; mt < 4; ++mt) {
        int c_lo = c0 + warp_m * 64 + mt * 16 + lr;
        int c_hi = c_lo + 8;
        float bias_lo = b_border[c_lo];
        float bias_hi = b_border[c_hi];
#pragma unroll
        for (int nt = 0; nt < 4; ++nt) {
            int p = hw0 + warp_n * 32 + nt * 8 + 2 * lq;
            float2 lo, hi;
            lo.x = fmaxf(acc[mt][nt][0] + bias_lo, 0.f);
            lo.y = fmaxf(acc[mt][nt][1] + bias_lo, 0.f);
            hi.x = fmaxf(acc[mt][nt][2] + bias_hi, 0.f);
            hi.y = fmaxf(acc[mt][nt][3] + bias_hi, 0.f);
            *(float2*)(out + ((size_t)n * COUT + c_lo) * HW + p) = lo;
            *(float2*)(out + ((size_t)n * COUT + c_hi) * HW + p) = hi;
        }
    }
}

// ============================================================================
extern "C" void kernel_launch(void* const* d_in, const int* in_sizes, int n_in,
                              void* d_out, int out_size)
{
    const float* feature  = (const float*)d_in[0];
    const float* boxes    = (const float*)d_in[1];
    // d_in[2] = wh (unused by forward)
    const float* w_cur    = (const float*)d_in[3];
    const float* b_cur    = (const float*)d_in[4];
    const float* w_ltrb   = (const float*)d_in[5];
    const float* b_ltrb   = (const float*)d_in[6];
    const float* w_mask   = (const float*)d_in[7];
    const float* b_mask   = (const float*)d_in[8];
    const float* w_border = (const float*)d_in[9];
    const float* b_border = (const float*)d_in[10];
    float* out = (float*)d_out;

    k_conv1<<<dim3(144, 5), 256>>>(feature, w_cur, b_cur, w_ltrb, b_ltrb);
    k_inorm<<<NB * C5, 256>>>();
    k_transpose<<<dim3(288, 16, NB), dim3(32, 8)>>>();
    k_border<<<NB * HW / 2, 128>>>(boxes);
    k_mask<<<dim3(144, 5), 256>>>(w_mask, b_mask);
    k_final<<<dim3(144, 2), 256>>>(w_border, b_border, out);
}

// round 7
// speedup vs baseline: 3.4988x; 1.2768x over previous
#include <cuda_runtime.h>
#include <math.h>
#include <stdint.h>

#define NB   2
#define CIN  256
#define Hh   96
#define Ww   96
#define HW   9216
#define BC   128
#define C4   512
#define C5   640
#define COUT 256
#define KMASK 4608   // 512*9

#define APITCH 20    // uint2 per A row (16 used + 4 pad); 20 % 16 == 4 -> conflict-free
#define BPITCH 132   // uint2 per B k-row; 132 % 16 == 4 -> conflict-free

// ---- scratch (static device arrays; no allocation) ----
__device__ float g_cv1[(size_t)NB*C5*HW];      // conv1x1 out: ch 0..127 = cur, 128..639 = ltrb (post-IN in place)
__device__ float g_f4t[(size_t)NB*4*HW*BC];    // feat4 transposed: [n][border][hw][c]
__device__ float g_ltrb[(size_t)NB*C4*HW];     // border-align output in the reshaped [n][512][HW] layout
__device__ float g_mask[(size_t)NB*C5*HW];     // sigmoid(conv3x3)

__device__ __forceinline__ uint32_t to_tf32(float x) {
    uint32_t y;
    asm("cvt.rna.tf32.f32 %0, %1;" : "=r"(y) : "f"(x));
    return y;
}

__device__ __forceinline__ void mma_tf32(float* c, const uint32_t* a, const uint32_t* b) {
    asm volatile(
        "mma.sync.aligned.m16n8k8.row.col.f32.tf32.tf32.f32 "
        "{%0,%1,%2,%3}, {%4,%5,%6,%7}, {%8,%9}, {%0,%1,%2,%3};"
        : "+f"(c[0]), "+f"(c[1]), "+f"(c[2]), "+f"(c[3])
        : "r"(a[0]), "r"(a[1]), "r"(a[2]), "r"(a[3]), "r"(b[0]), "r"(b[1]));
}

// Shared tensor-core tile compute over paired-uint2 smem layouts.
// As2: [128][APITCH] uint2, pair {A[m][ks*8+lq], A[m][ks*8+lq+4]} at [m][ks*4+lq]
// Bs2: [16][BPITCH]  uint2, pair {B[ks*8+lq][col], B[ks*8+lq+4][col]} at [ks*4+lq][col]
__device__ __forceinline__ void gemm_tile(const uint2* As2, const uint2* Bs2,
    float acc[4][4][4], int warp_m, int warp_n, int lr, int lq)
{
#pragma unroll
    for (int ks = 0; ks < 4; ++ks) {
        const int kp = ks * 4 + lq;
        uint32_t afr[4][4], bfr[4][2];
#pragma unroll
        for (int mt = 0; mt < 4; ++mt) {
            int row = warp_m * 64 + mt * 16 + lr;
            uint2 alo = As2[row * APITCH + kp];
            uint2 ahi = As2[(row + 8) * APITCH + kp];
            afr[mt][0] = alo.x; afr[mt][1] = ahi.x;
            afr[mt][2] = alo.y; afr[mt][3] = ahi.y;
        }
#pragma unroll
        for (int nt = 0; nt < 4; ++nt) {
            int col = warp_n * 32 + nt * 8 + lr;
            uint2 b = Bs2[kp * BPITCH + col];
            bfr[nt][0] = b.x; bfr[nt][1] = b.y;
        }
#pragma unroll
        for (int mt = 0; mt < 4; ++mt)
#pragma unroll
            for (int nt = 0; nt < 4; ++nt)
                mma_tf32(acc[mt][nt], afr[mt], bfr[nt]);
    }
}

// ============================================================================
// K1: fused conv1x1 (cur||ltrb) = GEMM [640,256]x[256,HW] + bias, tf32 mma.
// ============================================================================
__global__ __launch_bounds__(256) void k_conv1(const float* __restrict__ feat,
    const float* __restrict__ w_cur, const float* __restrict__ b_cur,
    const float* __restrict__ w_ltrb, const float* __restrict__ b_ltrb)
{
    __shared__ uint2 As2[128 * APITCH];
    __shared__ uint2 Bs2[16 * BPITCH];
    const int c0  = blockIdx.y * 128;
    const int p0  = blockIdx.x * 128;
    const int n   = p0 / HW;
    const int hw0 = p0 - n * HW;
    const float* X = feat + (size_t)n * CIN * HW + hw0;
    const int tid  = threadIdx.x;
    const int lane = tid & 31;
    const int wid  = tid >> 5;
    const int warp_m = wid & 1;
    const int warp_n = wid >> 1;
    const int lr = lane >> 2;
    const int lq = lane & 3;

    // staging maps (loop-invariant per thread)
    const int am  = tid >> 4;                       // A: row base (+16j)
    const int app = tid & 15;                       // A: pair slot
    const int aklo = ((app >> 2) << 3) + (app & 3); // A: k_lo within tile
    const int bcol = tid & 127;                     // B: column
    const int bprb = tid >> 7;                      // B: pair-row base (+2j)

    float acc[4][4][4];
#pragma unroll
    for (int mt = 0; mt < 4; ++mt)
#pragma unroll
        for (int nt = 0; nt < 4; ++nt)
#pragma unroll
            for (int r = 0; r < 4; ++r) acc[mt][nt][r] = 0.f;

    float2 rA[8], rB[8];
    // prologue tile 0
#pragma unroll
    for (int j = 0; j < 8; ++j) {
        int m = am + 16 * j, c = c0 + m;
        const float* W = (c < BC) ? (w_cur + c * CIN) : (w_ltrb + (c - BC) * CIN);
        rA[j].x = W[aklo];
        rA[j].y = W[aklo + 4];
    }
#pragma unroll
    for (int j = 0; j < 8; ++j) {
        int pr = bprb + 2 * j;
        int klo = ((pr >> 2) << 3) + (pr & 3);
        rB[j].x = X[(size_t)klo * HW + bcol];
        rB[j].y = X[(size_t)(klo + 4) * HW + bcol];
    }

    const int NT = CIN / 32;
    for (int kt = 0; kt < NT; ++kt) {
#pragma unroll
        for (int j = 0; j < 8; ++j) {
            uint2 v; v.x = to_tf32(rA[j].x); v.y = to_tf32(rA[j].y);
            As2[(am + 16 * j) * APITCH + app] = v;
        }
#pragma unroll
        for (int j = 0; j < 8; ++j) {
            uint2 v; v.x = to_tf32(rB[j].x); v.y = to_tf32(rB[j].y);
            Bs2[(bprb + 2 * j) * BPITCH + bcol] = v;
        }
        __syncthreads();
        if (kt + 1 < NT) {
            int k0 = (kt + 1) * 32;
#pragma unroll
            for (int j = 0; j < 8; ++j) {
                int m = am + 16 * j, c = c0 + m;
                const float* W = (c < BC) ? (w_cur + c * CIN) : (w_ltrb + (c - BC) * CIN);
                rA[j].x = W[k0 + aklo];
                rA[j].y = W[k0 + aklo + 4];
            }
#pragma unroll
            for (int j = 0; j < 8; ++j) {
                int pr = bprb + 2 * j;
                int klo = k0 + ((pr >> 2) << 3) + (pr & 3);
                rB[j].x = X[(size_t)klo * HW + bcol];
                rB[j].y = X[(size_t)(klo + 4) * HW + bcol];
            }
        }
        gemm_tile(As2, Bs2, acc, warp_m, warp_n, lr, lq);
        __syncthreads();
    }

#pragma unroll
    for (int mt = 0; mt < 4; ++mt) {
        int c_lo = c0 + warp_m * 64 + mt * 16 + lr;
        int c_hi = c_lo + 8;
        float bias_lo = (c_lo < BC) ? b_cur[c_lo] : b_ltrb[c_lo - BC];
        float bias_hi = (c_hi < BC) ? b_cur[c_hi] : b_ltrb[c_hi - BC];
#pragma unroll
        for (int nt = 0; nt < 4; ++nt) {
            int p = hw0 + warp_n * 32 + nt * 8 + 2 * lq;
            float2 lo, hi;
            lo.x = acc[mt][nt][0] + bias_lo;
            lo.y = acc[mt][nt][1] + bias_lo;
            hi.x = acc[mt][nt][2] + bias_hi;
            hi.y = acc[mt][nt][3] + bias_hi;
            *(float2*)(g_cv1 + ((size_t)n * C5 + c_lo) * HW + p) = lo;
            *(float2*)(g_cv1 + ((size_t)n * C5 + c_hi) * HW + p) = hi;
        }
    }
}

// ============================================================================
// K2: instance norm (biased var, eps=1e-5) + ReLU, in place. One block per (n,c).
// ============================================================================
__global__ __launch_bounds__(256) void k_inorm()
{
    const int nc = blockIdx.x;          // n*C5 + c
    float4* base = (float4*)(g_cv1 + (size_t)nc * HW);
    const int tid = threadIdx.x;
    float s = 0.f, q = 0.f;
#pragma unroll
    for (int i = tid; i < HW / 4; i += 256) {
        float4 v = base[i];
        s += v.x + v.y + v.z + v.w;
        q += v.x * v.x + v.y * v.y + v.z * v.z + v.w * v.w;
    }
    __shared__ float ss[256], qq[256];
    ss[tid] = s; qq[tid] = q;
    __syncthreads();
    for (int off = 128; off > 0; off >>= 1) {
        if (tid < off) { ss[tid] += ss[tid + off]; qq[tid] += qq[tid + off]; }
        __syncthreads();
    }
    const float mean = ss[0] * (1.f / HW);
    const float var  = qq[0] * (1.f / HW) - mean * mean;
    const float rstd = rsqrtf(var + 1e-5f);
#pragma unroll
    for (int i = tid; i < HW / 4; i += 256) {
        float4 v = base[i];
        v.x = fmaxf((v.x - mean) * rstd, 0.f);
        v.y = fmaxf((v.y - mean) * rstd, 0.f);
        v.z = fmaxf((v.z - mean) * rstd, 0.f);
        v.w = fmaxf((v.w - mean) * rstd, 0.f);
        base[i] = v;
    }
}

// ============================================================================
// K2b: transpose feat4 (channels 128..639 of g_cv1) into [n][b][hw][c]
// ============================================================================
__global__ void k_transpose()
{
    __shared__ float t[32][33];
    const int n   = blockIdx.z;
    const int c0  = blockIdx.y * 32;    // 0..511 relative to feat4
    const int hw0 = blockIdx.x * 32;
    const int tx = threadIdx.x, ty = threadIdx.y;   // 32 x 8
    const float* src = g_cv1 + ((size_t)n * C5 + BC + c0) * HW + hw0;
#pragma unroll
    for (int r = 0; r < 4; ++r)
        t[ty + r * 8][tx] = src[(size_t)(ty + r * 8) * HW + tx];
    __syncthreads();
    const int b   = c0 >> 7;
    const int cc0 = c0 & 127;
    float* dst = g_f4t + (((size_t)n * 4 + b) * HW + hw0) * BC + cc0;
#pragma unroll
    for (int r = 0; r < 4; ++r)
        dst[(size_t)(ty + r * 8) * BC + tx] = t[tx][ty + r * 8];
}

// ============================================================================
// K3: BorderAlign. 2 pixels per block; threads 0..87 precompute sample params;
// each thread then handles 2 channels (float2 gathers) for one pixel.
// ============================================================================
struct SampP { int o00, o01, o10, o11; float w00, w01, w10, w11; };

__global__ __launch_bounds__(128) void k_border(const float* __restrict__ boxes)
{
    __shared__ SampP sp[2][44];
    const int blk = blockIdx.x;         // pixel pair
    const int t  = threadIdx.x;

    if (t < 88) {
        const int pix = t / 44, s = t - pix * 44;
        const int b = s / 11, i = s - b * 11;
        const int P = blk * 2 + pix;
        const int n = P / HW, hw = P - n * HW;
        const float4 bx = *(const float4*)(boxes + ((size_t)n * HW + hw) * 4);
        const float bw = (bx.z - bx.x) * 0.1f, bh = (bx.w - bx.y) * 0.1f;
        const float sx = (b == 3) ? bx.z : bx.x;
        const float sy = (b == 2) ? bx.w : bx.y;
        const float dx = (b == 0 || b == 2) ? bw : 0.f;
        const float dy = (b == 1 || b == 3) ? bh : 0.f;
        const float x = sx + dx * (float)i;
        const float y = sy + dy * (float)i;
        const bool valid = (x >= -1.f) && (x <= 96.f) && (y >= -1.f) && (y <= 96.f);
        const float xc = fminf(fmaxf(x, 0.f), 95.f);
        const float yc = fminf(fmaxf(y, 0.f), 95.f);
        int x0 = (int)floorf(xc); if (x0 > 95) x0 = 95;
        int y0 = (int)floorf(yc); if (y0 > 95) y0 = 95;
        const int x1i = x0 + 1 > 95 ? 95 : x0 + 1;
        const int y1i = y0 + 1 > 95 ? 95 : y0 + 1;
        const float lx = (x0 >= 95) ? 0.f : (xc - (float)x0);
        const float ly = (y0 >= 95) ? 0.f : (yc - (float)y0);
        const float hx = 1.f - lx, hy = 1.f - ly;
        const float sv = valid ? 1.f : 0.f;
        SampP p;
        p.o00 = (y0  * 96 + x0 ) * BC;
        p.o01 = (y0  * 96 + x1i) * BC;
        p.o10 = (y1i * 96 + x0 ) * BC;
        p.o11 = (y1i * 96 + x1i) * BC;
        p.w00 = hy * hx * sv;
        p.w01 = hy * lx * sv;
        p.w10 = ly * hx * sv;
        p.w11 = ly * lx * sv;
        sp[pix][s] = p;
    }
    __syncthreads();

    const int half = t >> 6;            // which pixel of the pair
    const int ch   = (t & 63) * 2;      // channel pair
    const int P = blk * 2 + half;
    const int n = P / HW, hw = P - n * HW;
    const float* ftn = g_f4t + (size_t)n * 4 * HW * BC + ch;
    float2 o[4];
#pragma unroll
    for (int b = 0; b < 4; ++b) {
        const float* fb = ftn + b * (HW * BC);
        float mx = -3.4e38f, my = -3.4e38f;
#pragma unroll
        for (int i = 0; i < 11; ++i) {
            const SampP p = sp[half][b * 11 + i];
            const float2 v00 = *(const float2*)(fb + p.o00);
            const float2 v01 = *(const float2*)(fb + p.o01);
            const float2 v10 = *(const float2*)(fb + p.o10);
            const float2 v11 = *(const float2*)(fb + p.o11);
            float vx = p.w00 * v00.x;
            vx = fmaf(p.w01, v01.x, vx);
            vx = fmaf(p.w10, v10.x, vx);
            vx = fmaf(p.w11, v11.x, vx);
            float vy = p.w00 * v00.y;
            vy = fmaf(p.w01, v01.y, vy);
            vy = fmaf(p.w10, v10.y, vy);
            vy = fmaf(p.w11, v11.y, vy);
            mx = fmaxf(mx, vx);
            my = fmaxf(my, vy);
        }
        o[b].x = mx; o[b].y = my;
    }
    float* base = g_ltrb + (size_t)n * C4 * HW;
    float4 r0; r0.x = o[0].x; r0.y = o[1].x; r0.z = o[2].x; r0.w = o[3].x;
    float4 r1; r1.x = o[0].y; r1.y = o[1].y; r1.z = o[2].y; r1.w = o[3].y;
    *(float4*)(base + ((size_t)ch       * HW + hw) * 4) = r0;
    *(float4*)(base + ((size_t)(ch + 1) * HW + hw) * 4) = r1;
}

// ============================================================================
// K4: conv3x3 (feat4 -> 640ch) implicit GEMM [640,4608]x[4608,HW], tf32 mma,
// paired-uint2 smem, sigmoid epilogue.
// ============================================================================
__global__ __launch_bounds__(256) void k_mask(const float* __restrict__ w_mask,
                                              const float* __restrict__ b_mask)
{
    __shared__ uint2 As2[128 * APITCH];
    __shared__ uint2 Bs2[16 * BPITCH];
    const int c0  = blockIdx.y * 128;
    const int p0  = blockIdx.x * 128;
    const int n   = p0 / HW;
    const int hw0 = p0 - n * HW;
    const float* F = g_cv1 + ((size_t)n * C5 + BC) * HW;   // feat4 (post IN+ReLU)
    const int tid  = threadIdx.x;
    const int lane = tid & 31;
    const int wid  = tid >> 5;
    const int warp_m = wid & 1;
    const int warp_n = wid >> 1;
    const int lr = lane >> 2;
    const int lq = lane & 3;

    const int am  = tid >> 4;
    const int app = tid & 15;
    const int aklo = ((app >> 2) << 3) + (app & 3);
    const int bcol = tid & 127;
    const int bprb = tid >> 7;
    const int phh = (hw0 + bcol) / 96;            // pixel h (loop-invariant)
    const int pww = (hw0 + bcol) - phh * 96;      // pixel w

    float acc[4][4][4];
#pragma unroll
    for (int mt = 0; mt < 4; ++mt)
#pragma unroll
        for (int nt = 0; nt < 4; ++nt)
#pragma unroll
            for (int r = 0; r < 4; ++r) acc[mt][nt][r] = 0.f;

    float2 rA[8], rB[8];

    auto gatherB = [&](int kk) -> float {
        int ci = kk / 9;
        int tap = kk - ci * 9;
        int dy = tap / 3 - 1;
        int dx = tap - (tap / 3) * 3 - 1;
        int hh = phh + dy, ww = pww + dx;
        float v = 0.f;
        if ((unsigned)hh < 96u && (unsigned)ww < 96u)
            v = F[(size_t)ci * HW + hh * 96 + ww];
        return v;
    };

    // prologue tile 0
#pragma unroll
    for (int j = 0; j < 8; ++j) {
        int m = am + 16 * j;
        const float* W = w_mask + (size_t)(c0 + m) * KMASK;
        rA[j].x = W[aklo];
        rA[j].y = W[aklo + 4];
    }
#pragma unroll
    for (int j = 0; j < 8; ++j) {
        int pr = bprb + 2 * j;
        int klo = ((pr >> 2) << 3) + (pr & 3);
        rB[j].x = gatherB(klo);
        rB[j].y = gatherB(klo + 4);
    }

    const int NT = KMASK / 32;
    for (int kt = 0; kt < NT; ++kt) {
#pragma unroll
        for (int j = 0; j < 8; ++j) {
            uint2 v; v.x = to_tf32(rA[j].x); v.y = to_tf32(rA[j].y);
            As2[(am + 16 * j) * APITCH + app] = v;
        }
#pragma unroll
        for (int j = 0; j < 8; ++j) {
            uint2 v; v.x = to_tf32(rB[j].x); v.y = to_tf32(rB[j].y);
            Bs2[(bprb + 2 * j) * BPITCH + bcol] = v;
        }
        __syncthreads();
        if (kt + 1 < NT) {
            int k0 = (kt + 1) * 32;
#pragma unroll
            for (int j = 0; j < 8; ++j) {
                int m = am + 16 * j;
                const float* W = w_mask + (size_t)(c0 + m) * KMASK + k0;
                rA[j].x = W[aklo];
                rA[j].y = W[aklo + 4];
            }
#pragma unroll
            for (int j = 0; j < 8; ++j) {
                int pr = bprb + 2 * j;
                int klo = k0 + ((pr >> 2) << 3) + (pr & 3);
                rB[j].x = gatherB(klo);
                rB[j].y = gatherB(klo + 4);
            }
        }
        gemm_tile(As2, Bs2, acc, warp_m, warp_n, lr, lq);
        __syncthreads();
    }

#pragma unroll
    for (int mt = 0; mt < 4; ++mt) {
        int c_lo = c0 + warp_m * 64 + mt * 16 + lr;
        int c_hi = c_lo + 8;
        float bias_lo = b_mask[c_lo];
        float bias_hi = b_mask[c_hi];
#pragma unroll
        for (int nt = 0; nt < 4; ++nt) {
            int p = hw0 + warp_n * 32 + nt * 8 + 2 * lq;
            float v0 = acc[mt][nt][0] + bias_lo;
            float v1 = acc[mt][nt][1] + bias_lo;
            float v2 = acc[mt][nt][2] + bias_hi;
            float v3 = acc[mt][nt][3] + bias_hi;
            float2 lo, hi;
            lo.x = 1.f / (1.f + __expf(-v0));
            lo.y = 1.f / (1.f + __expf(-v1));
            hi.x = 1.f / (1.f + __expf(-v2));
            hi.y = 1.f / (1.f + __expf(-v3));
            *(float2*)(g_mask + ((size_t)n * C5 + c_lo) * HW + p) = lo;
            *(float2*)(g_mask + ((size_t)n * C5 + c_hi) * HW + p) = hi;
        }
    }
}

// ============================================================================
// K5: final conv1x1 [256,640] on (align*mask), tf32 mma, paired smem, ReLU.
// ============================================================================
__global__ __launch_bounds__(256) void k_final(const float* __restrict__ w_border,
    const float* __restrict__ b_border, float* __restrict__ out)
{
    __shared__ uint2 As2[128 * APITCH];
    __shared__ uint2 Bs2[16 * BPITCH];
    const int c0  = blockIdx.y * 128;
    const int p0  = blockIdx.x * 128;
    const int n   = p0 / HW;
    const int hw0 = p0 - n * HW;
    const int tid  = threadIdx.x;
    const int lane = tid & 31;
    const int wid  = tid >> 5;
    const int warp_m = wid & 1;
    const int warp_n = wid >> 1;
    const int lr = lane >> 2;
    const int lq = lane & 3;

    const int am  = tid >> 4;
    const int app = tid & 15;
    const int aklo = ((app >> 2) << 3) + (app & 3);
    const int bcol = tid & 127;
    const int bprb = tid >> 7;

    const float* ltrb_n = g_ltrb + (size_t)n * C4 * HW + hw0 + bcol;
    const float* fms_n  = g_cv1  + (size_t)n * C5 * HW + hw0 + bcol;  // ch0..127 = fm_short
    const float* mask_n = g_mask + (size_t)n * C5 * HW + hw0 + bcol;

    auto loadB = [&](int kk) -> float {
        float a = (kk < C4) ? ltrb_n[(size_t)kk * HW]
                            : fms_n[(size_t)(kk - C4) * HW];
        return a * mask_n[(size_t)kk * HW];
    };

    float acc[4][4][4];
#pragma unroll
    for (int mt = 0; mt < 4; ++mt)
#pragma unroll
        for (int nt = 0; nt < 4; ++nt)
#pragma unroll
            for (int r = 0; r < 4; ++r) acc[mt][nt][r] = 0.f;

    float2 rA[8], rB[8];
#pragma unroll
    for (int j = 0; j < 8; ++j) {
        int m = am + 16 * j;
        const float* W = w_border + (size_t)(c0 + m) * C5;
        rA[j].x = W[aklo];
        rA[j].y = W[aklo + 4];
    }
#pragma unroll
    for (int j = 0; j < 8; ++j) {
        int pr = bprb + 2 * j;
        int klo = ((pr >> 2) << 3) + (pr & 3);
        rB[j].x = loadB(klo);
        rB[j].y = loadB(klo + 4);
    }

    const int NT = C5 / 32;
    for (int kt = 0; kt < NT; ++kt) {
#pragma unroll
        for (int j = 0; j < 8; ++j) {
            uint2 v; v.x = to_tf32(rA[j].x); v.y = to_tf32(rA[j].y);
            As2[(am + 16 * j) * APITCH + app] = v;
        }
#pragma unroll
        for (int j = 0; j < 8; ++j) {
            uint2 v; v.x = to_tf32(rB[j].x); v.y = to_tf32(rB[j].y);
            Bs2[(bprb + 2 * j) * BPITCH + bcol] = v;
        }
        __syncthreads();
        if (kt + 1 < NT) {
            int k0 = (kt + 1) * 32;
#pragma unroll
            for (int j = 0; j < 8; ++j) {
                int m = am + 16 * j;
                const float* W = w_border + (size_t)(c0 + m) * C5 + k0;
                rA[j].x = W[aklo];
                rA[j].y = W[aklo + 4];
            }
#pragma unroll
            for (int j = 0; j < 8; ++j) {
                int pr = bprb + 2 * j;
                int klo = k0 + ((pr >> 2) << 3) + (pr & 3);
                rB[j].x = loadB(klo);
                rB[j].y = loadB(klo + 4);
            }
        }
        gemm_tile(As2, Bs2, acc, warp_m, warp_n, lr, lq);
        __syncthreads();
    }

#pragma unroll
    for (int mt = 0; mt < 4; ++mt) {
        int c_lo = c0 + warp_m * 64 + mt * 16 + lr;
        int c_hi = c_lo + 8;
        float bias_lo = b_border[c_lo];
        float bias_hi = b_border[c_hi];
#pragma unroll
        for (int nt = 0; nt < 4; ++nt) {
            int p = hw0 + warp_n * 32 + nt * 8 + 2 * lq;
            float2 lo, hi;
            lo.x = fmaxf(acc[mt][nt][0] + bias_lo, 0.f);
            lo.y = fmaxf(acc[mt][nt][1] + bias_lo, 0.f);
            hi.x = fmaxf(acc[mt][nt][2] + bias_hi, 0.f);
            hi.y = fmaxf(acc[mt][nt][3] + bias_hi, 0.f);
            *(float2*)(out + ((size_t)n * COUT + c_lo) * HW + p) = lo;
            *(float2*)(out + ((size_t)n * COUT + c_hi) * HW + p) = hi;
        }
    }
}

// ============================================================================
extern "C" void kernel_launch(void* const* d_in, const int* in_sizes, int n_in,
                              void* d_out, int out_size)
{
    const float* feature  = (const float*)d_in[0];
    const float* boxes    = (const float*)d_in[1];
    // d_in[2] = wh (unused by forward)
    const float* w_cur    = (const float*)d_in[3];
    const float* b_cur    = (const float*)d_in[4];
    const float* w_ltrb   = (const float*)d_in[5];
    const float* b_ltrb   = (const float*)d_in[6];
    const float* w_mask   = (const float*)d_in[7];
    const float* b_mask   = (const float*)d_in[8];
    const float* w_border = (const float*)d_in[9];
    const float* b_border = (const float*)d_in[10];
    float* out = (float*)d_out;

    k_conv1<<<dim3(144, 5), 256>>>(feature, w_cur, b_cur, w_ltrb, b_ltrb);
    k_inorm<<<NB * C5, 256>>>();
    k_transpose<<<dim3(288, 16, NB), dim3(32, 8)>>>();
    k_border<<<NB * HW / 2, 128>>>(boxes);
    k_mask<<<dim3(144, 5), 256>>>(w_mask, b_mask);
    k_final<<<dim3(144, 2), 256>>>(w_border, b_border, out);
}

// round 9
// speedup vs baseline: 3.7264x; 1.0651x over previous
#include <cuda_runtime.h>
#include <math.h>
#include <stdint.h>

#define NB   2
#define CIN  256
#define Hh   96
#define Ww   96
#define HW   9216
#define BC   128
#define C4   512
#define C5   640
#define COUT 256
#define KMASK 4608   // 512*9

#define APITCH 20    // uint2 per A row (16 used + 4 pad); 20 % 16 == 4 -> conflict-free
#define BPITCH 132   // uint2 per B k-row; 132 % 16 == 4 -> conflict-free

// ---- scratch (static device arrays; no allocation) ----
__device__ float g_cv1[(size_t)NB*C5*HW];      // conv1x1 out: ch 0..127 = cur, 128..639 = ltrb (post-IN in place)
__device__ float g_f4t[(size_t)NB*4*HW*BC];    // feat4 transposed: [n][border][hw][c]
__device__ float g_ltrb[(size_t)NB*C4*HW];     // border-align output in the reshaped [n][512][HW] layout
__device__ float g_mask[(size_t)NB*C5*HW];     // sigmoid(conv3x3)

__device__ __forceinline__ uint32_t to_tf32(float x) {
    uint32_t y;
    asm("cvt.rna.tf32.f32 %0, %1;" : "=r"(y) : "f"(x));
    return y;
}

__device__ __forceinline__ void mma_tf32(float* c, const uint32_t* a, const uint32_t* b) {
    asm volatile(
        "mma.sync.aligned.m16n8k8.row.col.f32.tf32.tf32.f32 "
        "{%0,%1,%2,%3}, {%4,%5,%6,%7}, {%8,%9}, {%0,%1,%2,%3};"
        : "+f"(c[0]), "+f"(c[1]), "+f"(c[2]), "+f"(c[3])
        : "r"(a[0]), "r"(a[1]), "r"(a[2]), "r"(a[3]), "r"(b[0]), "r"(b[1]));
}

// Tile compute for the 8-warp / 64x32-warp-tile kernels (k_conv1, k_final).
__device__ __forceinline__ void gemm_tile(const uint2* As2, const uint2* Bs2,
    float acc[4][4][4], int warp_m, int warp_n, int lr, int lq)
{
#pragma unroll
    for (int ks = 0; ks < 4; ++ks) {
        const int kp = ks * 4 + lq;
        uint32_t afr[4][4], bfr[4][2];
#pragma unroll
        for (int mt = 0; mt < 4; ++mt) {
            int row = warp_m * 64 + mt * 16 + lr;
            uint2 alo = As2[row * APITCH + kp];
            uint2 ahi = As2[(row + 8) * APITCH + kp];
            afr[mt][0] = alo.x; afr[mt][1] = ahi.x;
            afr[mt][2] = alo.y; afr[mt][3] = ahi.y;
        }
#pragma unroll
        for (int nt = 0; nt < 4; ++nt) {
            int col = warp_n * 32 + nt * 8 + lr;
            uint2 b = Bs2[kp * BPITCH + col];
            bfr[nt][0] = b.x; bfr[nt][1] = b.y;
        }
#pragma unroll
        for (int mt = 0; mt < 4; ++mt)
#pragma unroll
            for (int nt = 0; nt < 4; ++nt)
                mma_tf32(acc[mt][nt], afr[mt], bfr[nt]);
    }
}

// ============================================================================
// K1: fused conv1x1 (cur||ltrb) = GEMM [640,256]x[256,HW] + bias, tf32 mma.
// ============================================================================
__global__ __launch_bounds__(256) void k_conv1(const float* __restrict__ feat,
    const float* __restrict__ w_cur, const float* __restrict__ b_cur,
    const float* __restrict__ w_ltrb, const float* __restrict__ b_ltrb)
{
    __shared__ uint2 As2[128 * APITCH];
    __shared__ uint2 Bs2[16 * BPITCH];
    const int c0  = blockIdx.y * 128;
    const int p0  = blockIdx.x * 128;
    const int n   = p0 / HW;
    const int hw0 = p0 - n * HW;
    const float* X = feat + (size_t)n * CIN * HW + hw0;
    const int tid  = threadIdx.x;
    const int lane = tid & 31;
    const int wid  = tid >> 5;
    const int warp_m = wid & 1;
    const int warp_n = wid >> 1;
    const int lr = lane >> 2;
    const int lq = lane & 3;

    const int am  = tid >> 4;
    const int app = tid & 15;
    const int aklo = ((app >> 2) << 3) + (app & 3);
    const int bcol = tid & 127;
    const int bprb = tid >> 7;

    float acc[4][4][4];
#pragma unroll
    for (int mt = 0; mt < 4; ++mt)
#pragma unroll
        for (int nt = 0; nt < 4; ++nt)
#pragma unroll
            for (int r = 0; r < 4; ++r) acc[mt][nt][r] = 0.f;

    float2 rA[8], rB[8];
#pragma unroll
    for (int j = 0; j < 8; ++j) {
        int m = am + 16 * j, c = c0 + m;
        const float* W = (c < BC) ? (w_cur + c * CIN) : (w_ltrb + (c - BC) * CIN);
        rA[j].x = W[aklo];
        rA[j].y = W[aklo + 4];
    }
#pragma unroll
    for (int j = 0; j < 8; ++j) {
        int pr = bprb + 2 * j;
        int klo = ((pr >> 2) << 3) + (pr & 3);
        rB[j].x = X[(size_t)klo * HW + bcol];
        rB[j].y = X[(size_t)(klo + 4) * HW + bcol];
    }

    const int NT = CIN / 32;
    for (int kt = 0; kt < NT; ++kt) {
#pragma unroll
        for (int j = 0; j < 8; ++j) {
            uint2 v; v.x = to_tf32(rA[j].x); v.y = to_tf32(rA[j].y);
            As2[(am + 16 * j) * APITCH + app] = v;
        }
#pragma unroll
        for (int j = 0; j < 8; ++j) {
            uint2 v; v.x = to_tf32(rB[j].x); v.y = to_tf32(rB[j].y);
            Bs2[(bprb + 2 * j) * BPITCH + bcol] = v;
        }
        __syncthreads();
        if (kt + 1 < NT) {
            int k0 = (kt + 1) * 32;
#pragma unroll
            for (int j = 0; j < 8; ++j) {
                int m = am + 16 * j, c = c0 + m;
                const float* W = (c < BC) ? (w_cur + c * CIN) : (w_ltrb + (c - BC) * CIN);
                rA[j].x = W[k0 + aklo];
                rA[j].y = W[k0 + aklo + 4];
            }
#pragma unroll
            for (int j = 0; j < 8; ++j) {
                int pr = bprb + 2 * j;
                int klo = k0 + ((pr >> 2) << 3) + (pr & 3);
                rB[j].x = X[(size_t)klo * HW + bcol];
                rB[j].y = X[(size_t)(klo + 4) * HW + bcol];
            }
        }
        gemm_tile(As2, Bs2, acc, warp_m, warp_n, lr, lq);
        __syncthreads();
    }

#pragma unroll
    for (int mt = 0; mt < 4; ++mt) {
        int c_lo = c0 + warp_m * 64 + mt * 16 + lr;
        int c_hi = c_lo + 8;
        float bias_lo = (c_lo < BC) ? b_cur[c_lo] : b_ltrb[c_lo - BC];
        float bias_hi = (c_hi < BC) ? b_cur[c_hi] : b_ltrb[c_hi - BC];
#pragma unroll
        for (int nt = 0; nt < 4; ++nt) {
            int p = hw0 + warp_n * 32 + nt * 8 + 2 * lq;
            float2 lo, hi;
            lo.x = acc[mt][nt][0] + bias_lo;
            lo.y = acc[mt][nt][1] + bias_lo;
            hi.x = acc[mt][nt][2] + bias_hi;
            hi.y = acc[mt][nt][3] + bias_hi;
            *(float2*)(g_cv1 + ((size_t)n * C5 + c_lo) * HW + p) = lo;
            *(float2*)(g_cv1 + ((size_t)n * C5 + c_hi) * HW + p) = hi;
        }
    }
}

// ============================================================================
// K2: instance norm (biased var, eps=1e-5) + ReLU, in place. One block per (n,c).
// ============================================================================
__global__ __launch_bounds__(256) void k_inorm()
{
    const int nc = blockIdx.x;          // n*C5 + c
    float4* base = (float4*)(g_cv1 + (size_t)nc * HW);
    const int tid = threadIdx.x;
    float s = 0.f, q = 0.f;
#pragma unroll
    for (int i = tid; i < HW / 4; i += 256) {
        float4 v = base[i];
        s += v.x + v.y + v.z + v.w;
        q += v.x * v.x + v.y * v.y + v.z * v.z + v.w * v.w;
    }
    __shared__ float ss[256], qq[256];
    ss[tid] = s; qq[tid] = q;
    __syncthreads();
    for (int off = 128; off > 0; off >>= 1) {
        if (tid < off) { ss[tid] += ss[tid + off]; qq[tid] += qq[tid + off]; }
        __syncthreads();
    }
    const float mean = ss[0] * (1.f / HW);
    const float var  = qq[0] * (1.f / HW) - mean * mean;
    const float rstd = rsqrtf(var + 1e-5f);
#pragma unroll
    for (int i = tid; i < HW / 4; i += 256) {
        float4 v = base[i];
        v.x = fmaxf((v.x - mean) * rstd, 0.f);
        v.y = fmaxf((v.y - mean) * rstd, 0.f);
        v.z = fmaxf((v.z - mean) * rstd, 0.f);
        v.w = fmaxf((v.w - mean) * rstd, 0.f);
        base[i] = v;
    }
}

// ============================================================================
// K2b: transpose feat4 (channels 128..639 of g_cv1) into [n][b][hw][c]
// ============================================================================
__global__ void k_transpose()
{
    __shared__ float t[32][33];
    const int n   = blockIdx.z;
    const int c0  = blockIdx.y * 32;    // 0..511 relative to feat4
    const int hw0 = blockIdx.x * 32;
    const int tx = threadIdx.x, ty = threadIdx.y;   // 32 x 8
    const float* src = g_cv1 + ((size_t)n * C5 + BC + c0) * HW + hw0;
#pragma unroll
    for (int r = 0; r < 4; ++r)
        t[ty + r * 8][tx] = src[(size_t)(ty + r * 8) * HW + tx];
    __syncthreads();
    const int b   = c0 >> 7;
    const int cc0 = c0 & 127;
    float* dst = g_f4t + (((size_t)n * 4 + b) * HW + hw0) * BC + cc0;
#pragma unroll
    for (int r = 0; r < 4; ++r)
        dst[(size_t)(ty + r * 8) * BC + tx] = t[tx][ty + r * 8];
}

// ============================================================================
// K3: BorderAlign. 2 pixels per block; threads 0..87 precompute sample params;
// each thread then handles 2 channels (float2 gathers) for one pixel.
// ============================================================================
struct SampP { int o00, o01, o10, o11; float w00, w01, w10, w11; };

__global__ __launch_bounds__(128) void k_border(const float* __restrict__ boxes)
{
    __shared__ SampP sp[2][44];
    const int blk = blockIdx.x;         // pixel pair
    const int t  = threadIdx.x;

    if (t < 88) {
        const int pix = t / 44, s = t - pix * 44;
        const int b = s / 11, i = s - b * 11;
        const int P = blk * 2 + pix;
        const int n = P / HW, hw = P - n * HW;
        const float4 bx = *(const float4*)(boxes + ((size_t)n * HW + hw) * 4);
        const float bw = (bx.z - bx.x) * 0.1f, bh = (bx.w - bx.y) * 0.1f;
        const float sx = (b == 3) ? bx.z : bx.x;
        const float sy = (b == 2) ? bx.w : bx.y;
        const float dx = (b == 0 || b == 2) ? bw : 0.f;
        const float dy = (b == 1 || b == 3) ? bh : 0.f;
        const float x = sx + dx * (float)i;
        const float y = sy + dy * (float)i;
        const bool valid = (x >= -1.f) && (x <= 96.f) && (y >= -1.f) && (y <= 96.f);
        const float xc = fminf(fmaxf(x, 0.f), 95.f);
        const float yc = fminf(fmaxf(y, 0.f), 95.f);
        int x0 = (int)floorf(xc); if (x0 > 95) x0 = 95;
        int y0 = (int)floorf(yc); if (y0 > 95) y0 = 95;
        const int x1i = x0 + 1 > 95 ? 95 : x0 + 1;
        const int y1i = y0 + 1 > 95 ? 95 : y0 + 1;
        const float lx = (x0 >= 95) ? 0.f : (xc - (float)x0);
        const float ly = (y0 >= 95) ? 0.f : (yc - (float)y0);
        const float hx = 1.f - lx, hy = 1.f - ly;
        const float sv = valid ? 1.f : 0.f;
        SampP p;
        p.o00 = (y0  * 96 + x0 ) * BC;
        p.o01 = (y0  * 96 + x1i) * BC;
        p.o10 = (y1i * 96 + x0 ) * BC;
        p.o11 = (y1i * 96 + x1i) * BC;
        p.w00 = hy * hx * sv;
        p.w01 = hy * lx * sv;
        p.w10 = ly * hx * sv;
        p.w11 = ly * lx * sv;
        sp[pix][s] = p;
    }
    __syncthreads();

    const int half = t >> 6;            // which pixel of the pair
    const int ch   = (t & 63) * 2;      // channel pair
    const int P = blk * 2 + half;
    const int n = P / HW, hw = P - n * HW;
    const float* ftn = g_f4t + (size_t)n * 4 * HW * BC + ch;
    float2 o[4];
#pragma unroll
    for (int b = 0; b < 4; ++b) {
        const float* fb = ftn + b * (HW * BC);
        float mx = -3.4e38f, my = -3.4e38f;
#pragma unroll
        for (int i = 0; i < 11; ++i) {
            const SampP p = sp[half][b * 11 + i];
            const float2 v00 = *(const float2*)(fb + p.o00);
            const float2 v01 = *(const float2*)(fb + p.o01);
            const float2 v10 = *(const float2*)(fb + p.o10);
            const float2 v11 = *(const float2*)(fb + p.o11);
            float vx = p.w00 * v00.x;
            vx = fmaf(p.w01, v01.x, vx);
            vx = fmaf(p.w10, v10.x, vx);
            vx = fmaf(p.w11, v11.x, vx);
            float vy = p.w00 * v00.y;
            vy = fmaf(p.w01, v01.y, vy);
            vy = fmaf(p.w10, v10.y, vy);
            vy = fmaf(p.w11, v11.y, vy);
            mx = fmaxf(mx, vx);
            my = fmaxf(my, vy);
        }
        o[b].x = mx; o[b].y = my;
    }
    float* base = g_ltrb + (size_t)n * C4 * HW;
    float4 r0; r0.x = o[0].x; r0.y = o[1].x; r0.z = o[2].x; r0.w = o[3].x;
    float4 r1; r1.x = o[0].y; r1.y = o[1].y; r1.z = o[2].y; r1.w = o[3].y;
    *(float4*)(base + ((size_t)ch       * HW + hw) * 4) = r0;
    *(float4*)(base + ((size_t)(ch + 1) * HW + hw) * 4) = r1;
}

// ============================================================================
// K4: conv3x3 (feat4 -> 640ch) implicit GEMM [640,4608]x[4608,HW], tf32 mma.
// 4 warps, warp tile 64x64 (mt=4, nt=8): 16 LDS.64 per 32 MMAs per k-step
// (0.5 loads/MMA vs 0.75 in the 8-warp layout). Block tile 128x128x32.
// ============================================================================
__global__ __launch_bounds__(128) void k_mask(const float* __restrict__ w_mask,
                                              const float* __restrict__ b_mask)
{
    __shared__ uint2 As2[128 * APITCH];
    __shared__ uint2 Bs2[16 * BPITCH];
    const int c0  = blockIdx.y * 128;
    const int p0  = blockIdx.x * 128;
    const int n   = p0 / HW;
    const int hw0 = p0 - n * HW;
    const float* F = g_cv1 + ((size_t)n * C5 + BC) * HW;   // feat4 (post IN+ReLU)
    const int tid  = threadIdx.x;          // 0..127
    const int lane = tid & 31;
    const int wid  = tid >> 5;             // 0..3
    const int warp_m = wid & 1;            // M offset 0/64
    const int warp_n = wid >> 1;           // N offset 0/64
    const int lr = lane >> 2;
    const int lq = lane & 3;

    // staging maps: A -> 16 pair-slots (rows am+8j), B -> 16 pair-rows at col tid
    const int am  = tid >> 4;              // 0..7
    const int app = tid & 15;
    const int aklo = ((app >> 2) << 3) + (app & 3);
    const int bcol = tid;                  // 0..127
    const int phh0 = (hw0 + bcol) / 96;
    const int pww0 = (hw0 + bcol) - phh0 * 96;

    auto gB = [&](int kk) -> float {
        int ci = kk / 9;
        int tap = kk - ci * 9;
        int dy = tap / 3 - 1;
        int dx = tap - (tap / 3) * 3 - 1;
        int hh = phh0 + dy, ww = pww0 + dx;
        float v = 0.f;
        if ((unsigned)hh < 96u && (unsigned)ww < 96u)
            v = F[(size_t)ci * HW + hh * 96 + ww];
        return v;
    };

    float acc[4][8][4];
#pragma unroll
    for (int mt = 0; mt < 4; ++mt)
#pragma unroll
        for (int nt = 0; nt < 8; ++nt)
#pragma unroll
            for (int r = 0; r < 4; ++r) acc[mt][nt][r] = 0.f;

    float2 rA[16], rB[16];
    // prologue tile 0
#pragma unroll
    for (int j = 0; j < 16; ++j) {
        const float* W = w_mask + (size_t)(c0 + am + 8 * j) * KMASK;
        rA[j].x = W[aklo];
        rA[j].y = W[aklo + 4];
    }
#pragma unroll
    for (int pr = 0; pr < 16; ++pr) {
        int klo = ((pr >> 2) << 3) + (pr & 3);
        rB[pr].x = gB(klo);
        rB[pr].y = gB(klo + 4);
    }

    const int NT = KMASK / 32;   // 144
    for (int kt = 0; kt < NT; ++kt) {
#pragma unroll
        for (int j = 0; j < 16; ++j) {
            uint2 v; v.x = to_tf32(rA[j].x); v.y = to_tf32(rA[j].y);
            As2[(am + 8 * j) * APITCH + app] = v;
        }
#pragma unroll
        for (int pr = 0; pr < 16; ++pr) {
            uint2 v; v.x = to_tf32(rB[pr].x); v.y = to_tf32(rB[pr].y);
            Bs2[pr * BPITCH + bcol] = v;
        }
        __syncthreads();
        if (kt + 1 < NT) {
            const int k0n = (kt + 1) * 32;
#pragma unroll
            for (int j = 0; j < 16; ++j) {
                const float* W = w_mask + (size_t)(c0 + am + 8 * j) * KMASK + k0n;
                rA[j].x = W[aklo];
                rA[j].y = W[aklo + 4];
            }
#pragma unroll
            for (int pr = 0; pr < 16; ++pr) {
                int klo = k0n + ((pr >> 2) << 3) + (pr & 3);
                rB[pr].x = gB(klo);
                rB[pr].y = gB(klo + 4);
            }
        }
#pragma unroll
        for (int ks = 0; ks < 4; ++ks) {
            const int kp = ks * 4 + lq;
            uint32_t afr[4][4], bfr[8][2];
#pragma unroll
            for (int mt = 0; mt < 4; ++mt) {
                int row = warp_m * 64 + mt * 16 + lr;
                uint2 alo = As2[row * APITCH + kp];
                uint2 ahi = As2[(row + 8) * APITCH + kp];
                afr[mt][0] = alo.x; afr[mt][1] = ahi.x;
                afr[mt][2] = alo.y; afr[mt][3] = ahi.y;
            }
#pragma unroll
            for (int nt = 0; nt < 8; ++nt) {
                int col = warp_n * 64 + nt * 8 + lr;
                uint2 b = Bs2[kp * BPITCH + col];
                bfr[nt][0] = b.x; bfr[nt][1] = b.y;
            }
#pragma unroll
            for (int mt = 0; mt < 4; ++mt)
#pragma unroll
                for (int nt = 0; nt < 8; ++nt)
                    mma_tf32(acc[mt][nt], afr[mt], bfr[nt]);
        }
        __syncthreads();
    }

#pragma unroll
    for (int mt = 0; mt < 4; ++mt) {
        int c_lo = c0 + warp_m * 64 + mt * 16 + lr;
        int c_hi = c_lo + 8;
        float bias_lo = b_mask[c_lo];
        float bias_hi = b_mask[c_hi];
#pragma unroll
        for (int nt = 0; nt < 8; ++nt) {
            int p = hw0 + warp_n * 64 + nt * 8 + 2 * lq;
            float v0 = acc[mt][nt][0] + bias_lo;
            float v1 = acc[mt][nt][1] + bias_lo;
            float v2 = acc[mt][nt][2] + bias_hi;
            float v3 = acc[mt][nt][3] + bias_hi;
            float2 lo, hi;
            lo.x = 1.f / (1.f + __expf(-v0));
            lo.y = 1.f / (1.f + __expf(-v1));
            hi.x = 1.f / (1.f + __expf(-v2));
            hi.y = 1.f / (1.f + __expf(-v3));
            *(float2*)(g_mask + ((size_t)n * C5 + c_lo) * HW + p) = lo;
            *(float2*)(g_mask + ((size_t)n * C5 + c_hi) * HW + p) = hi;
        }
    }
}

// ============================================================================
// K5: final conv1x1 [256,640] on (align*mask), tf32 mma, paired smem, ReLU.
// ============================================================================
__global__ __launch_bounds__(256) void k_final(const float* __restrict__ w_border,
    const float* __restrict__ b_border, float* __restrict__ out)
{
    __shared__ uint2 As2[128 * APITCH];
    __shared__ uint2 Bs2[16 * BPITCH];
    const int c0  = blockIdx.y * 128;
    const int p0  = blockIdx.x * 128;
    const int n   = p0 / HW;
    const int hw0 = p0 - n * HW;
    const int tid  = threadIdx.x;
    const int lane = tid & 31;
    const int wid  = tid >> 5;
    const int warp_m = wid & 1;
    const int warp_n = wid >> 1;
    const int lr = lane >> 2;
    const int lq = lane & 3;

    const int am  = tid >> 4;
    const int app = tid & 15;
    const int aklo = ((app >> 2) << 3) + (app & 3);
    const int bcol = tid & 127;
    const int bprb = tid >> 7;

    const float* ltrb_n = g_ltrb + (size_t)n * C4 * HW + hw0 + bcol;
    const float* fms_n  = g_cv1  + (size_t)n * C5 * HW + hw0 + bcol;  // ch0..127 = fm_short
    const float* mask_n = g_mask + (size_t)n * C5 * HW + hw0 + bcol;

    auto loadB = [&](int kk) -> float {
        float a = (kk < C4) ? ltrb_n[(size_t)kk * HW]
                            : fms_n[(size_t)(kk - C4) * HW];
        return a * mask_n[(size_t)kk * HW];
    };

    float acc[4][4][4];
#pragma unroll
    for (int mt = 0; mt < 4; ++mt)
#pragma unroll
        for (int nt = 0; nt < 4; ++nt)
#pragma unroll
            for (int r = 0; r < 4; ++r) acc[mt][nt][r] = 0.f;

    float2 rA[8], rB[8];
#pragma unroll
    for (int j = 0; j < 8; ++j) {
        int m = am + 16 * j;
        const float* W = w_border + (size_t)(c0 + m) * C5;
        rA[j].x = W[aklo];
        rA[j].y = W[aklo + 4];
    }
#pragma unroll
    for (int j = 0; j < 8; ++j) {
        int pr = bprb + 2 * j;
        int klo = ((pr >> 2) << 3) + (pr & 3);
        rB[j].x = loadB(klo);
        rB[j].y = loadB(klo + 4);
    }

    const int NT = C5 / 32;
    for (int kt = 0; kt < NT; ++kt) {
#pragma unroll
        for (int j = 0; j < 8; ++j) {
            uint2 v; v.x = to_tf32(rA[j].x); v.y = to_tf32(rA[j].y);
            As2[(am + 16 * j) * APITCH + app] = v;
        }
#pragma unroll
        for (int j = 0; j < 8; ++j) {
            uint2 v; v.x = to_tf32(rB[j].x); v.y = to_tf32(rB[j].y);
            Bs2[(bprb + 2 * j) * BPITCH + bcol] = v;
        }
        __syncthreads();
        if (kt + 1 < NT) {
            int k0 = (kt + 1) * 32;
#pragma unroll
            for (int j = 0; j < 8; ++j) {
                int m = am + 16 * j;
                const float* W = w_border + (size_t)(c0 + m) * C5 + k0;
                rA[j].x = W[aklo];
                rA[j].y = W[aklo + 4];
            }
#pragma unroll
            for (int j = 0; j < 8; ++j) {
                int pr = bprb + 2 * j;
                int klo = k0 + ((pr >> 2) << 3) + (pr & 3);
                rB[j].x = loadB(klo);
                rB[j].y = loadB(klo + 4);
            }
        }
        gemm_tile(As2, Bs2, acc, warp_m, warp_n, lr, lq);
        __syncthreads();
    }

#pragma unroll
    for (int mt = 0; mt < 4; ++mt) {
        int c_lo = c0 + warp_m * 64 + mt * 16 + lr;
        int c_hi = c_lo + 8;
        float bias_lo = b_border[c_lo];
        float bias_hi = b_border[c_hi];
#pragma unroll
        for (int nt = 0; nt < 4; ++nt) {
            int p = hw0 + warp_n * 32 + nt * 8 + 2 * lq;
            float2 lo, hi;
            lo.x = fmaxf(acc[mt][nt][0] + bias_lo, 0.f);
            lo.y = fmaxf(acc[mt][nt][1] + bias_lo, 0.f);
            hi.x = fmaxf(acc[mt][nt][2] + bias_hi, 0.f);
            hi.y = fmaxf(acc[mt][nt][3] + bias_hi, 0.f);
            *(float2*)(out + ((size_t)n * COUT + c_lo) * HW + p) = lo;
            *(float2*)(out + ((size_t)n * COUT + c_hi) * HW + p) = hi;
        }
    }
}

// ============================================================================
extern "C" void kernel_launch(void* const* d_in, const int* in_sizes, int n_in,
                              void* d_out, int out_size)
{
    const float* feature  = (const float*)d_in[0];
    const float* boxes    = (const float*)d_in[1];
    // d_in[2] = wh (unused by forward)
    const float* w_cur    = (const float*)d_in[3];
    const float* b_cur    = (const float*)d_in[4];
    const float* w_ltrb   = (const float*)d_in[5];
    const float* b_ltrb   = (const float*)d_in[6];
    const float* w_mask   = (const float*)d_in[7];
    const float* b_mask   = (const float*)d_in[8];
    const float* w_border = (const float*)d_in[9];
    const float* b_border = (const float*)d_in[10];
    float* out = (float*)d_out;

    k_conv1<<<dim3(144, 5), 256>>>(feature, w_cur, b_cur, w_ltrb, b_ltrb);
    k_inorm<<<NB * C5, 256>>>();
    k_transpose<<<dim3(288, 16, NB), dim3(32, 8)>>>();
    k_border<<<NB * HW / 2, 128>>>(boxes);
    k_mask<<<dim3(144, 5), 128>>>(w_mask, b_mask);
    k_final<<<dim3(144, 2), 256>>>(w_border, b_border, out);
}

// round 12
// speedup vs baseline: 3.7994x; 1.0196x over previous
#include <cuda_runtime.h>
#include <math.h>
#include <stdint.h>

#define NB   2
#define CIN  256
#define Hh   96
#define Ww   96
#define HW   9216
#define BC   128
#define C4   512
#define C5   640
#define COUT 256
#define KMASK 4608   // 512*9

#define APITCH 20    // uint2 per A row (16 used + 4 pad); 20 % 16 == 4 -> conflict-free
#define BPITCH 132   // uint2 per B k-row; 132 % 16 == 4 -> conflict-free

// ---- scratch (static device arrays; no allocation) ----
__device__ float g_cv1[(size_t)NB*C5*HW];      // conv1x1 out: ch 0..127 = cur, 128..639 = ltrb (post-IN in place)
__device__ float g_f4t[(size_t)NB*4*HW*BC];    // feat4 transposed: [n][border][hw][c]
__device__ float g_ltrb[(size_t)NB*C4*HW];     // border-align output in the reshaped [n][512][HW] layout
__device__ float g_mask[(size_t)NB*C5*HW];     // sigmoid(conv3x3)

__device__ __forceinline__ uint32_t to_tf32(float x) {
    uint32_t y;
    asm("cvt.rna.tf32.f32 %0, %1;" : "=r"(y) : "f"(x));
    return y;
}

__device__ __forceinline__ void mma_tf32(float* c, const uint32_t* a, const uint32_t* b) {
    asm volatile(
        "mma.sync.aligned.m16n8k8.row.col.f32.tf32.tf32.f32 "
        "{%0,%1,%2,%3}, {%4,%5,%6,%7}, {%8,%9}, {%0,%1,%2,%3};"
        : "+f"(c[0]), "+f"(c[1]), "+f"(c[2]), "+f"(c[3])
        : "r"(a[0]), "r"(a[1]), "r"(a[2]), "r"(a[3]), "r"(b[0]), "r"(b[1]));
}

// 4-warp tile compute: warp tile 64(M) x 64(N), block tile 128x128x32.
// 16 LDS.64 per 32 MMAs per k-step (0.5 loads/MMA).
__device__ __forceinline__ void gemm_tile64(const uint2* As2, const uint2* Bs2,
    float acc[4][8][4], int warp_m, int warp_n, int lr, int lq)
{
#pragma unroll
    for (int ks = 0; ks < 4; ++ks) {
        const int kp = ks * 4 + lq;
        uint32_t afr[4][4], bfr[8][2];
#pragma unroll
        for (int mt = 0; mt < 4; ++mt) {
            int row = warp_m * 64 + mt * 16 + lr;
            uint2 alo = As2[row * APITCH + kp];
            uint2 ahi = As2[(row + 8) * APITCH + kp];
            afr[mt][0] = alo.x; afr[mt][1] = ahi.x;
            afr[mt][2] = alo.y; afr[mt][3] = ahi.y;
        }
#pragma unroll
        for (int nt = 0; nt < 8; ++nt) {
            int col = warp_n * 64 + nt * 8 + lr;
            uint2 b = Bs2[kp * BPITCH + col];
            bfr[nt][0] = b.x; bfr[nt][1] = b.y;
        }
#pragma unroll
        for (int mt = 0; mt < 4; ++mt)
#pragma unroll
            for (int nt = 0; nt < 8; ++nt)
                mma_tf32(acc[mt][nt], afr[mt], bfr[nt]);
    }
}

// ============================================================================
// K1: fused conv1x1 (cur||ltrb) = GEMM [640,256]x[256,HW] + bias, tf32 mma.
// 4 warps, warp tile 64x64.
// ============================================================================
__global__ __launch_bounds__(128) void k_conv1(const float* __restrict__ feat,
    const float* __restrict__ w_cur, const float* __restrict__ b_cur,
    const float* __restrict__ w_ltrb, const float* __restrict__ b_ltrb)
{
    __shared__ uint2 As2[128 * APITCH];
    __shared__ uint2 Bs2[16 * BPITCH];
    const int c0  = blockIdx.y * 128;
    const int p0  = blockIdx.x * 128;
    const int n   = p0 / HW;
    const int hw0 = p0 - n * HW;
    const float* X = feat + (size_t)n * CIN * HW + hw0;
    const int tid  = threadIdx.x;          // 0..127
    const int lane = tid & 31;
    const int wid  = tid >> 5;
    const int warp_m = wid & 1;
    const int warp_n = wid >> 1;
    const int lr = lane >> 2;
    const int lq = lane & 3;

    const int am  = tid >> 4;              // 0..7
    const int app = tid & 15;
    const int aklo = ((app >> 2) << 3) + (app & 3);
    const int bcol = tid;                  // 0..127

    float acc[4][8][4];
#pragma unroll
    for (int mt = 0; mt < 4; ++mt)
#pragma unroll
        for (int nt = 0; nt < 8; ++nt)
#pragma unroll
            for (int r = 0; r < 4; ++r) acc[mt][nt][r] = 0.f;

    float2 rA[16], rB[16];
#pragma unroll
    for (int j = 0; j < 16; ++j) {
        int c = c0 + am + 8 * j;
        const float* W = (c < BC) ? (w_cur + c * CIN) : (w_ltrb + (c - BC) * CIN);
        rA[j].x = W[aklo];
        rA[j].y = W[aklo + 4];
    }
#pragma unroll
    for (int pr = 0; pr < 16; ++pr) {
        int klo = ((pr >> 2) << 3) + (pr & 3);
        rB[pr].x = X[(size_t)klo * HW + bcol];
        rB[pr].y = X[(size_t)(klo + 4) * HW + bcol];
    }

    const int NT = CIN / 32;
    for (int kt = 0; kt < NT; ++kt) {
#pragma unroll
        for (int j = 0; j < 16; ++j) {
            uint2 v; v.x = to_tf32(rA[j].x); v.y = to_tf32(rA[j].y);
            As2[(am + 8 * j) * APITCH + app] = v;
        }
#pragma unroll
        for (int pr = 0; pr < 16; ++pr) {
            uint2 v; v.x = to_tf32(rB[pr].x); v.y = to_tf32(rB[pr].y);
            Bs2[pr * BPITCH + bcol] = v;
        }
        __syncthreads();
        if (kt + 1 < NT) {
            int k0 = (kt + 1) * 32;
#pragma unroll
            for (int j = 0; j < 16; ++j) {
                int c = c0 + am + 8 * j;
                const float* W = (c < BC) ? (w_cur + c * CIN) : (w_ltrb + (c - BC) * CIN);
                rA[j].x = W[k0 + aklo];
                rA[j].y = W[k0 + aklo + 4];
            }
#pragma unroll
            for (int pr = 0; pr < 16; ++pr) {
                int klo = k0 + ((pr >> 2) << 3) + (pr & 3);
                rB[pr].x = X[(size_t)klo * HW + bcol];
                rB[pr].y = X[(size_t)(klo + 4) * HW + bcol];
            }
        }
        gemm_tile64(As2, Bs2, acc, warp_m, warp_n, lr, lq);
        __syncthreads();
    }

#pragma unroll
    for (int mt = 0; mt < 4; ++mt) {
        int c_lo = c0 + warp_m * 64 + mt * 16 + lr;
        int c_hi = c_lo + 8;
        float bias_lo = (c_lo < BC) ? b_cur[c_lo] : b_ltrb[c_lo - BC];
        float bias_hi = (c_hi < BC) ? b_cur[c_hi] : b_ltrb[c_hi - BC];
#pragma unroll
        for (int nt = 0; nt < 8; ++nt) {
            int p = hw0 + warp_n * 64 + nt * 8 + 2 * lq;
            float2 lo, hi;
            lo.x = acc[mt][nt][0] + bias_lo;
            lo.y = acc[mt][nt][1] + bias_lo;
            hi.x = acc[mt][nt][2] + bias_hi;
            hi.y = acc[mt][nt][3] + bias_hi;
            *(float2*)(g_cv1 + ((size_t)n * C5 + c_lo) * HW + p) = lo;
            *(float2*)(g_cv1 + ((size_t)n * C5 + c_hi) * HW + p) = hi;
        }
    }
}

// ============================================================================
// K2: instance norm (biased var, eps=1e-5) + ReLU, in place. One block per (n,c).
// ============================================================================
__global__ __launch_bounds__(256) void k_inorm()
{
    const int nc = blockIdx.x;          // n*C5 + c
    float4* base = (float4*)(g_cv1 + (size_t)nc * HW);
    const int tid = threadIdx.x;
    float s = 0.f, q = 0.f;
#pragma unroll
    for (int i = tid; i < HW / 4; i += 256) {
        float4 v = base[i];
        s += v.x + v.y + v.z + v.w;
        q += v.x * v.x + v.y * v.y + v.z * v.z + v.w * v.w;
    }
    __shared__ float ss[256], qq[256];
    ss[tid] = s; qq[tid] = q;
    __syncthreads();
    for (int off = 128; off > 0; off >>= 1) {
        if (tid < off) { ss[tid] += ss[tid + off]; qq[tid] += qq[tid + off]; }
        __syncthreads();
    }
    const float mean = ss[0] * (1.f / HW);
    const float var  = qq[0] * (1.f / HW) - mean * mean;
    const float rstd = rsqrtf(var + 1e-5f);
#pragma unroll
    for (int i = tid; i < HW / 4; i += 256) {
        float4 v = base[i];
        v.x = fmaxf((v.x - mean) * rstd, 0.f);
        v.y = fmaxf((v.y - mean) * rstd, 0.f);
        v.z = fmaxf((v.z - mean) * rstd, 0.f);
        v.w = fmaxf((v.w - mean) * rstd, 0.f);
        base[i] = v;
    }
}

// ============================================================================
// K2b: transpose feat4 (channels 128..639 of g_cv1) into [n][b][hw][c]
// ============================================================================
__global__ void k_transpose()
{
    __shared__ float t[32][33];
    const int n   = blockIdx.z;
    const int c0  = blockIdx.y * 32;    // 0..511 relative to feat4
    const int hw0 = blockIdx.x * 32;
    const int tx = threadIdx.x, ty = threadIdx.y;   // 32 x 8
    const float* src = g_cv1 + ((size_t)n * C5 + BC + c0) * HW + hw0;
#pragma unroll
    for (int r = 0; r < 4; ++r)
        t[ty + r * 8][tx] = src[(size_t)(ty + r * 8) * HW + tx];
    __syncthreads();
    const int b   = c0 >> 7;
    const int cc0 = c0 & 127;
    float* dst = g_f4t + (((size_t)n * 4 + b) * HW + hw0) * BC + cc0;
#pragma unroll
    for (int r = 0; r < 4; ++r)
        dst[(size_t)(ty + r * 8) * BC + tx] = t[tx][ty + r * 8];
}

// ============================================================================
// K3: BorderAlign. 4 pixels per block; params precomputed to smem; each thread
// handles 4 channels (float4 gathers) for one pixel.
// ============================================================================
struct SampP { int o00, o01, o10, o11; float w00, w01, w10, w11; };

__global__ __launch_bounds__(128) void k_border(const float* __restrict__ boxes)
{
    __shared__ SampP sp[4][44];
    const int blk = blockIdx.x;         // pixel quad
    const int t  = threadIdx.x;

    for (int s = t; s < 176; s += 128) {
        const int pix = s / 44, q = s - pix * 44;
        const int b = q / 11, i = q - b * 11;
        const int P = blk * 4 + pix;
        const int n = P / HW, hw = P - n * HW;
        const float4 bx = *(const float4*)(boxes + ((size_t)n * HW + hw) * 4);
        const float bw = (bx.z - bx.x) * 0.1f, bh = (bx.w - bx.y) * 0.1f;
        const float sx = (b == 3) ? bx.z : bx.x;
        const float sy = (b == 2) ? bx.w : bx.y;
        const float dx = (b == 0 || b == 2) ? bw : 0.f;
        const float dy = (b == 1 || b == 3) ? bh : 0.f;
        const float x = sx + dx * (float)i;
        const float y = sy + dy * (float)i;
        const bool valid = (x >= -1.f) && (x <= 96.f) && (y >= -1.f) && (y <= 96.f);
        const float xc = fminf(fmaxf(x, 0.f), 95.f);
        const float yc = fminf(fmaxf(y, 0.f), 95.f);
        int x0 = (int)floorf(xc); if (x0 > 95) x0 = 95;
        int y0 = (int)floorf(yc); if (y0 > 95) y0 = 95;
        const int x1i = x0 + 1 > 95 ? 95 : x0 + 1;
        const int y1i = y0 + 1 > 95 ? 95 : y0 + 1;
        const float lx = (x0 >= 95) ? 0.f : (xc - (float)x0);
        const float ly = (y0 >= 95) ? 0.f : (yc - (float)y0);
        const float hx = 1.f - lx, hy = 1.f - ly;
        const float sv = valid ? 1.f : 0.f;
        SampP p;
        p.o00 = (y0  * 96 + x0 ) * BC;
        p.o01 = (y0  * 96 + x1i) * BC;
        p.o10 = (y1i * 96 + x0 ) * BC;
        p.o11 = (y1i * 96 + x1i) * BC;
        p.w00 = hy * hx * sv;
        p.w01 = hy * lx * sv;
        p.w10 = ly * hx * sv;
        p.w11 = ly * lx * sv;
        sp[pix][q] = p;
    }
    __syncthreads();

    const int half = t >> 5;            // pixel 0..3
    const int ch   = (t & 31) * 4;      // channel quad
    const int P = blk * 4 + half;
    const int n = P / HW, hw = P - n * HW;
    const float* ftn = g_f4t + (size_t)n * 4 * HW * BC + ch;
    float4 o[4];
#pragma unroll
    for (int b = 0; b < 4; ++b) {
        const float* fb = ftn + b * (HW * BC);
        float m0 = -3.4e38f, m1 = -3.4e38f, m2 = -3.4e38f, m3 = -3.4e38f;
#pragma unroll
        for (int i = 0; i < 11; ++i) {
            const SampP p = sp[half][b * 11 + i];
            const float4 v00 = *(const float4*)(fb + p.o00);
            const float4 v01 = *(const float4*)(fb + p.o01);
            const float4 v10 = *(const float4*)(fb + p.o10);
            const float4 v11 = *(const float4*)(fb + p.o11);
            float a0 = p.w00 * v00.x;
            a0 = fmaf(p.w01, v01.x, a0);
            a0 = fmaf(p.w10, v10.x, a0);
            a0 = fmaf(p.w11, v11.x, a0);
            float a1 = p.w00 * v00.y;
            a1 = fmaf(p.w01, v01.y, a1);
            a1 = fmaf(p.w10, v10.y, a1);
            a1 = fmaf(p.w11, v11.y, a1);
            float a2 = p.w00 * v00.z;
            a2 = fmaf(p.w01, v01.z, a2);
            a2 = fmaf(p.w10, v10.z, a2);
            a2 = fmaf(p.w11, v11.z, a2);
            float a3 = p.w00 * v00.w;
            a3 = fmaf(p.w01, v01.w, a3);
            a3 = fmaf(p.w10, v10.w, a3);
            a3 = fmaf(p.w11, v11.w, a3);
            m0 = fmaxf(m0, a0);
            m1 = fmaxf(m1, a1);
            m2 = fmaxf(m2, a2);
            m3 = fmaxf(m3, a3);
        }
        o[b].x = m0; o[b].y = m1; o[b].z = m2; o[b].w = m3;
    }
    float* base = g_ltrb + (size_t)n * C4 * HW;
    float4 r0; r0.x = o[0].x; r0.y = o[1].x; r0.z = o[2].x; r0.w = o[3].x;
    float4 r1; r1.x = o[0].y; r1.y = o[1].y; r1.z = o[2].y; r1.w = o[3].y;
    float4 r2; r2.x = o[0].z; r2.y = o[1].z; r2.z = o[2].z; r2.w = o[3].z;
    float4 r3; r3.x = o[0].w; r3.y = o[1].w; r3.z = o[2].w; r3.w = o[3].w;
    *(float4*)(base + ((size_t)(ch    ) * HW + hw) * 4) = r0;
    *(float4*)(base + ((size_t)(ch + 1) * HW + hw) * 4) = r1;
    *(float4*)(base + ((size_t)(ch + 2) * HW + hw) * 4) = r2;
    *(float4*)(base + ((size_t)(ch + 3) * HW + hw) * 4) = r3;
}

// ============================================================================
// K4: conv3x3 (feat4 -> 640ch) implicit GEMM [640,4608]x[4608,HW], tf32 mma.
// 4 warps, warp tile 64x64.
// ============================================================================
__global__ __launch_bounds__(128) void k_mask(const float* __restrict__ w_mask,
                                              const float* __restrict__ b_mask)
{
    __shared__ uint2 As2[128 * APITCH];
    __shared__ uint2 Bs2[16 * BPITCH];
    const int c0  = blockIdx.y * 128;
    const int p0  = blockIdx.x * 128;
    const int n   = p0 / HW;
    const int hw0 = p0 - n * HW;
    const float* F = g_cv1 + ((size_t)n * C5 + BC) * HW;   // feat4 (post IN+ReLU)
    const int tid  = threadIdx.x;          // 0..127
    const int lane = tid & 31;
    const int wid  = tid >> 5;             // 0..3
    const int warp_m = wid & 1;
    const int warp_n = wid >> 1;
    const int lr = lane >> 2;
    const int lq = lane & 3;

    const int am  = tid >> 4;              // 0..7
    const int app = tid & 15;
    const int aklo = ((app >> 2) << 3) + (app & 3);
    const int bcol = tid;                  // 0..127
    const int phh0 = (hw0 + bcol) / 96;
    const int pww0 = (hw0 + bcol) - phh0 * 96;

    auto gB = [&](int kk) -> float {
        int ci = kk / 9;
        int tap = kk - ci * 9;
        int dy = tap / 3 - 1;
        int dx = tap - (tap / 3) * 3 - 1;
        int hh = phh0 + dy, ww = pww0 + dx;
        float v = 0.f;
        if ((unsigned)hh < 96u && (unsigned)ww < 96u)
            v = F[(size_t)ci * HW + hh * 96 + ww];
        return v;
    };

    float acc[4][8][4];
#pragma unroll
    for (int mt = 0; mt < 4; ++mt)
#pragma unroll
        for (int nt = 0; nt < 8; ++nt)
#pragma unroll
            for (int r = 0; r < 4; ++r) acc[mt][nt][r] = 0.f;

    float2 rA[16], rB[16];
#pragma unroll
    for (int j = 0; j < 16; ++j) {
        const float* W = w_mask + (size_t)(c0 + am + 8 * j) * KMASK;
        rA[j].x = W[aklo];
        rA[j].y = W[aklo + 4];
    }
#pragma unroll
    for (int pr = 0; pr < 16; ++pr) {
        int klo = ((pr >> 2) << 3) + (pr & 3);
        rB[pr].x = gB(klo);
        rB[pr].y = gB(klo + 4);
    }

    const int NT = KMASK / 32;   // 144
    for (int kt = 0; kt < NT; ++kt) {
#pragma unroll
        for (int j = 0; j < 16; ++j) {
            uint2 v; v.x = to_tf32(rA[j].x); v.y = to_tf32(rA[j].y);
            As2[(am + 8 * j) * APITCH + app] = v;
        }
#pragma unroll
        for (int pr = 0; pr < 16; ++pr) {
            uint2 v; v.x = to_tf32(rB[pr].x); v.y = to_tf32(rB[pr].y);
            Bs2[pr * BPITCH + bcol] = v;
        }
        __syncthreads();
        if (kt + 1 < NT) {
            const int k0n = (kt + 1) * 32;
#pragma unroll
            for (int j = 0; j < 16; ++j) {
                const float* W = w_mask + (size_t)(c0 + am + 8 * j) * KMASK + k0n;
                rA[j].x = W[aklo];
                rA[j].y = W[aklo + 4];
            }
#pragma unroll
            for (int pr = 0; pr < 16; ++pr) {
                int klo = k0n + ((pr >> 2) << 3) + (pr & 3);
                rB[pr].x = gB(klo);
                rB[pr].y = gB(klo + 4);
            }
        }
        gemm_tile64(As2, Bs2, acc, warp_m, warp_n, lr, lq);
        __syncthreads();
    }

#pragma unroll
    for (int mt = 0; mt < 4; ++mt) {
        int c_lo = c0 + warp_m * 64 + mt * 16 + lr;
        int c_hi = c_lo + 8;
        float bias_lo = b_mask[c_lo];
        float bias_hi = b_mask[c_hi];
#pragma unroll
        for (int nt = 0; nt < 8; ++nt) {
            int p = hw0 + warp_n * 64 + nt * 8 + 2 * lq;
            float v0 = acc[mt][nt][0] + bias_lo;
            float v1 = acc[mt][nt][1] + bias_lo;
            float v2 = acc[mt][nt][2] + bias_hi;
            float v3 = acc[mt][nt][3] + bias_hi;
            float2 lo, hi;
            lo.x = 1.f / (1.f + __expf(-v0));
            lo.y = 1.f / (1.f + __expf(-v1));
            hi.x = 1.f / (1.f + __expf(-v2));
            hi.y = 1.f / (1.f + __expf(-v3));
            *(float2*)(g_mask + ((size_t)n * C5 + c_lo) * HW + p) = lo;
            *(float2*)(g_mask + ((size_t)n * C5 + c_hi) * HW + p) = hi;
        }
    }
}

// ============================================================================
// K5: final conv1x1 [256,640] on (align*mask), tf32 mma, 4 warps 64x64, ReLU.
// ============================================================================
__global__ __launch_bounds__(128) void k_final(const float* __restrict__ w_border,
    const float* __restrict__ b_border, float* __restrict__ out)
{
    __shared__ uint2 As2[128 * APITCH];
    __shared__ uint2 Bs2[16 * BPITCH];
    const int c0  = blockIdx.y * 128;
    const int p0  = blockIdx.x * 128;
    const int n   = p0 / HW;
    const int hw0 = p0 - n * HW;
    const int tid  = threadIdx.x;          // 0..127
    const int lane = tid & 31;
    const int wid  = tid >> 5;
    const int warp_m = wid & 1;
    const int warp_n = wid >> 1;
    const int lr = lane >> 2;
    const int lq = lane & 3;

    const int am  = tid >> 4;
    const int app = tid & 15;
    const int aklo = ((app >> 2) << 3) + (app & 3);
    const int bcol = tid;

    const float* ltrb_n = g_ltrb + (size_t)n * C4 * HW + hw0 + bcol;
    const float* fms_n  = g_cv1  + (size_t)n * C5 * HW + hw0 + bcol;  // ch0..127 = fm_short
    const float* mask_n = g_mask + (size_t)n * C5 * HW + hw0 + bcol;

    auto loadB = [&](int kk) -> float {
        float a = (kk < C4) ? ltrb_n[(size_t)kk * HW]
                            : fms_n[(size_t)(kk - C4) * HW];
        return a * mask_n[(size_t)kk * HW];
    };

    float acc[4][8][4];
#pragma unroll
    for (int mt = 0; mt < 4; ++mt)
#pragma unroll
        for (int nt = 0; nt < 8; ++nt)
#pragma unroll
            for (int r = 0; r < 4; ++r) acc[mt][nt][r] = 0.f;

    float2 rA[16], rB[16];
#pragma unroll
    for (int j = 0; j < 16; ++j) {
        const float* W = w_border + (size_t)(c0 + am + 8 * j) * C5;
        rA[j].x = W[aklo];
        rA[j].y = W[aklo + 4];
    }
#pragma unroll
    for (int pr = 0; pr < 16; ++pr) {
        int klo = ((pr >> 2) << 3) + (pr & 3);
        rB[pr].x = loadB(klo);
        rB[pr].y = loadB(klo + 4);
    }

    const int NT = C5 / 32;
    for (int kt = 0; kt < NT; ++kt) {
#pragma unroll
        for (int j = 0; j < 16; ++j) {
            uint2 v; v.x = to_tf32(rA[j].x); v.y = to_tf32(rA[j].y);
            As2[(am + 8 * j) * APITCH + app] = v;
        }
#pragma unroll
        for (int pr = 0; pr < 16; ++pr) {
            uint2 v; v.x = to_tf32(rB[pr].x); v.y = to_tf32(rB[pr].y);
            Bs2[pr * BPITCH + bcol] = v;
        }
        __syncthreads();
        if (kt + 1 < NT) {
            int k0 = (kt + 1) * 32;
#pragma unroll
            for (int j = 0; j < 16; ++j) {
                const float* W = w_border + (size_t)(c0 + am + 8 * j) * C5 + k0;
                rA[j].x = W[aklo];
                rA[j].y = W[aklo + 4];
            }
#pragma unroll
            for (int pr = 0; pr < 16; ++pr) {
                int klo = k0 + ((pr >> 2) << 3) + (pr & 3);
                rB[pr].x = loadB(klo);
                rB[pr].y = loadB(klo + 4);
            }
        }
        gemm_tile64(As2, Bs2, acc, warp_m, warp_n, lr, lq);
        __syncthreads();
    }

#pragma unroll
    for (int mt = 0; mt < 4; ++mt) {
        int c_lo = c0 + warp_m * 64 + mt * 16 + lr;
        int c_hi = c_lo + 8;
        float bias_lo = b_border[c_lo];
        float bias_hi = b_border[c_hi];
#pragma unroll
        for (int nt = 0; nt < 8; ++nt) {
            int p = hw0 + warp_n * 64 + nt * 8 + 2 * lq;
            float2 lo, hi;
            lo.x = fmaxf(acc[mt][nt][0] + bias_lo, 0.f);
            lo.y = fmaxf(acc[mt][nt][1] + bias_lo, 0.f);
            hi.x = fmaxf(acc[mt][nt][2] + bias_hi, 0.f);
            hi.y = fmaxf(acc[mt][nt][3] + bias_hi, 0.f);
            *(float2*)(out + ((size_t)n * COUT + c_lo) * HW + p) = lo;
            *(float2*)(out + ((size_t)n * COUT + c_hi) * HW + p) = hi;
        }
    }
}

// ============================================================================
extern "C" void kernel_launch(void* const* d_in, const int* in_sizes, int n_in,
                              void* d_out, int out_size)
{
    const float* feature  = (const float*)d_in[0];
    const float* boxes    = (const float*)d_in[1];
    // d_in[2] = wh (unused by forward)
    const float* w_cur    = (const float*)d_in[3];
    const float* b_cur    = (const float*)d_in[4];
    const float* w_ltrb   = (const float*)d_in[5];
    const float* b_ltrb   = (const float*)d_in[6];
    const float* w_mask   = (const float*)d_in[7];
    const float* b_mask   = (const float*)d_in[8];
    const float* w_border = (const float*)d_in[9];
    const float* b_border = (const float*)d_in[10];
    float* out = (float*)d_out;

    k_conv1<<<dim3(144, 5), 128>>>(feature, w_cur, b_cur, w_ltrb, b_ltrb);
    k_inorm<<<NB * C5, 256>>>();
    k_transpose<<<dim3(288, 16, NB), dim3(32, 8)>>>();
    k_border<<<NB * HW / 4, 128>>>(boxes);
    k_mask<<<dim3(144, 5), 128>>>(w_mask, b_mask);
    k_final<<<dim3(144, 2), 128>>>(w_border, b_border, out);
}